// round 5
// baseline (speedup 1.0000x reference)
#include <cuda_runtime.h>
#include <cuda_bf16.h>
#include <cstdint>

// Shapes (fixed for this problem)
#define B_  8
#define T_  2048
#define C_  1024
#define NH  16
#define HS  64
#define NG  8
#define GT  256        // tokens per group
#define LQ  257        // GT + 1 mean token

// ---------------- device scratch (no allocations allowed) ----------------
__device__ float g_q[B_*NH*NG*GT*HS];
__device__ float g_k[B_*NH*NG*GT*HS];
__device__ float g_v[B_*NH*NG*GT*HS];
__device__ float g_qm[B_*NH*NG*HS];
__device__ float g_km[B_*NH*NG*HS];
__device__ float g_vm[B_*NH*NG*HS];
__device__ float g_attm[B_*NH*NG*HS];
__device__ float g_xo[B_*T_*C_];          // attn output (tf32-rounded), A of proj GEMM
__device__ float g_xr[B_*T_*C_];          // tf32-rounded x
__device__ float g_War[3*C_*C_];          // tf32-rounded W_attn [1024][3072]
__device__ float g_WpR[C_*C_];            // tf32-rounded W_proj [1024][1024]

// ---------------- helpers ----------------
__device__ __forceinline__ float tf32r(float x) {
    unsigned r;
    asm("cvt.rna.tf32.f32 %0, %1;" : "=r"(r) : "f"(x));
    return __uint_as_float(r);
}

__device__ __forceinline__ uint32_t smem_u32(const void* p) {
    uint32_t a;
    asm("{ .reg .u64 t; cvta.to.shared.u64 t, %1; cvt.u32.u64 %0, t; }" : "=r"(a) : "l"(p));
    return a;
}

__device__ __forceinline__ void cp16(uint32_t dst, const void* src) {
    asm volatile("cp.async.cg.shared.global [%0], [%1], 16;\n" :: "r"(dst), "l"(src));
}
#define CP_COMMIT() asm volatile("cp.async.commit_group;\n" ::: "memory")
#define CP_WAIT(n)  asm volatile("cp.async.wait_group %0;\n" :: "n"(n) : "memory")

__device__ __forceinline__ void mma_tf32(float& c0, float& c1, float& c2, float& c3,
                                         float a0, float a1, float a2, float a3,
                                         float b0, float b1) {
    asm volatile(
        "mma.sync.aligned.m16n8k8.row.col.f32.tf32.tf32.f32 "
        "{%0,%1,%2,%3}, {%4,%5,%6,%7}, {%8,%9}, {%0,%1,%2,%3};\n"
        : "+f"(c0), "+f"(c1), "+f"(c2), "+f"(c3)
        : "r"(__float_as_uint(a0)), "r"(__float_as_uint(a1)),
          "r"(__float_as_uint(a2)), "r"(__float_as_uint(a3)),
          "r"(__float_as_uint(b0)), "r"(__float_as_uint(b1)));
}

// ---------------- pre-rounding kernels (elementwise) ----------------
// which: 0 -> g_xr, 1 -> g_War, 2 -> g_WpR   (device globals resolved in device code!)
__global__ void round_kernel(const float* __restrict__ src, int which) {
    float* dst = (which == 0) ? g_xr : (which == 1) ? g_War : g_WpR;
    int i = (blockIdx.x * 256 + threadIdx.x) * 4;
    float4 v = *reinterpret_cast<const float4*>(src + i);
    v.x = tf32r(v.x); v.y = tf32r(v.y); v.z = tf32r(v.z); v.w = tf32r(v.w);
    *reinterpret_cast<float4*>(dst + i) = v;
}

// ---------------- pipelined tf32 GEMM: C[M,N] = A[M,K=1024] @ B[K,N] ----------------
// mode 0: A=g_xr, B=g_War (N=3072), epilogue scatters into g_q/g_k/g_v
// mode 1: A=g_xo, B=g_WpR (N=1024), epilogue writes row-major to Cout
#define BK 32
#define KCHUNKS 32                 // 1024 / 32
#define STAGES 3
#define A_STRIDE 36                // floats per A row
#define B_STRIDE 136               // floats per B row
#define A_STG (128 * A_STRIDE)     // 4608 floats
#define B_STG (BK * B_STRIDE)      // 4352 floats
#define STG_FLOATS (A_STG + B_STG) // 8960 floats = 35840 B

__global__ __launch_bounds__(256, 2)
void gemm_tf32_kernel(float* __restrict__ Cout, int N, int mode) {
    extern __shared__ float smemf[];
    const uint32_t smem_b = smem_u32(smemf);

    const float* __restrict__ A  = (mode == 0) ? g_xr  : g_xo;
    const float* __restrict__ Bm = (mode == 0) ? g_War : g_WpR;

    const int tid  = threadIdx.x;
    const int warp = tid >> 5;
    const int lane = tid & 31;
    const int wm   = warp & 1;      // 2 warps along M (64 each)
    const int wn   = warp >> 1;     // 4 warps along N (32 each)
    const int bm   = blockIdx.x * 128;
    const int bn   = blockIdx.y * 128;

    float acc[4][4][4];
#pragma unroll
    for (int mt = 0; mt < 4; mt++)
#pragma unroll
        for (int nt = 0; nt < 4; nt++)
#pragma unroll
            for (int i = 0; i < 4; i++) acc[mt][nt][i] = 0.f;

    // per-thread copy coordinates (A: 4 float4, B: 4 float4 per chunk)
    const int ar0 = tid >> 1;                 // 2 threads per A row
    const int as0 = (tid & 1) * 4;            // this thread does segs as0..as0+3
    const int br0 = tid >> 3;                 // 8 threads per B row (32 rows)
    const int bs0 = (tid & 7) * 4;            // this thread does segs bs0..bs0+3

    auto issue_copy = [&](int c, int s) {
        const int k0 = c * BK;
        const uint32_t sa = smem_b + (uint32_t)(s * STG_FLOATS) * 4u;
        const uint32_t sb = sa + (uint32_t)A_STG * 4u;
        const float* Asrc = A + (size_t)(bm + ar0) * 1024 + k0 + as0 * 4;
#pragma unroll
        for (int u = 0; u < 4; u++)
            cp16(sa + (uint32_t)(ar0 * A_STRIDE + (as0 + u) * 4) * 4u, Asrc + u * 4);
        const float* Bsrc = Bm + (size_t)(k0 + br0) * N + bn + bs0 * 4;
#pragma unroll
        for (int u = 0; u < 4; u++)
            cp16(sb + (uint32_t)(br0 * B_STRIDE + (bs0 + u) * 4) * 4u, Bsrc + u * 4);
        CP_COMMIT();
    };

    issue_copy(0, 0);
    issue_copy(1, 1);

    int stage = 0;
    for (int c = 0; c < KCHUNKS; c++) {
        if (c + 2 < KCHUNKS) { CP_WAIT(1); } else { CP_WAIT(0); }   // tail must drain fully
        __syncthreads();
        if (c + 2 < KCHUNKS) {
            int ns = stage + 2; if (ns >= STAGES) ns -= STAGES;
            issue_copy(c + 2, ns);
        }

        const float* As = smemf + stage * STG_FLOATS;
        const float* Bs = As + A_STG;

#pragma unroll
        for (int ks = 0; ks < 4; ks++) {
            float af[4][4];
            float bf[4][2];
            const int acol = ks * 8 + (lane & 3);
#pragma unroll
            for (int mt = 0; mt < 4; mt++) {
                const int row = wm * 64 + mt * 16 + (lane >> 2);
                af[mt][0] = As[row * A_STRIDE + acol];
                af[mt][1] = As[(row + 8) * A_STRIDE + acol];
                af[mt][2] = As[row * A_STRIDE + acol + 4];
                af[mt][3] = As[(row + 8) * A_STRIDE + acol + 4];
            }
            const int krow = ks * 8 + (lane & 3);
#pragma unroll
            for (int nt = 0; nt < 4; nt++) {
                const int ncol = wn * 32 + nt * 8 + (lane >> 2);
                bf[nt][0] = Bs[krow * B_STRIDE + ncol];
                bf[nt][1] = Bs[(krow + 4) * B_STRIDE + ncol];
            }
#pragma unroll
            for (int mt = 0; mt < 4; mt++)
#pragma unroll
                for (int nt = 0; nt < 4; nt++)
                    mma_tf32(acc[mt][nt][0], acc[mt][nt][1], acc[mt][nt][2], acc[mt][nt][3],
                             af[mt][0], af[mt][1], af[mt][2], af[mt][3],
                             bf[nt][0], bf[nt][1]);
        }
        __syncthreads();
        stage++; if (stage >= STAGES) stage = 0;
    }

    // ---- epilogue: float2 stores (cols (lane&3)*2, +1) ----
#pragma unroll
    for (int mt = 0; mt < 4; mt++) {
#pragma unroll
        for (int i2 = 0; i2 < 2; i2++) {          // c0c1 (row) / c2c3 (row+8)
            const int r = bm + wm * 64 + mt * 16 + (lane >> 2) + i2 * 8;
#pragma unroll
            for (int nt = 0; nt < 4; nt++) {
                const int c = bn + wn * 32 + nt * 8 + (lane & 3) * 2;
                float2 v = make_float2(acc[mt][nt][i2 * 2], acc[mt][nt][i2 * 2 + 1]);
                if (mode == 0) {
                    const int which = c >> 10, cc = c & 1023;
                    const int h = cc >> 6, d0 = cc & 63;
                    const int b = r >> 11, tg = r & 2047, g = tg >> 8, t = tg & 255;
                    float* base = (which == 0) ? g_q : (which == 1) ? g_k : g_v;
                    *reinterpret_cast<float2*>(
                        base + ((((size_t)b * NH + h) * NG + g) * GT + t) * HS + d0) = v;
                } else {
                    *reinterpret_cast<float2*>(Cout + (size_t)r * N + c) = v;
                }
            }
        }
    }
}

// ---------------- group means ----------------
__global__ void means_kernel() {
    int id = blockIdx.x;
    int d = threadIdx.x & 63;
    int which = threadIdx.x >> 6;
    const float* src = (which == 0) ? g_q : (which == 1) ? g_k : g_v;
    float* dst = (which == 0) ? g_qm : (which == 1) ? g_km : g_vm;
    size_t base = (size_t)id * (GT * HS);
    float s = 0.f;
#pragma unroll 8
    for (int t = 0; t < GT; t++) s += src[base + t * HS + d];
    dst[(size_t)id * HS + d] = s * (1.f / 256.f);
}

// ---------------- level-1 causal attention over 257 tokens ----------------
__global__ __launch_bounds__(256)
void attn_kernel() {
    extern __shared__ float sm[];
    float* Qs = sm;
    float* Ks = Qs + LQ * 65;
    float* Vs = Ks + LQ * 65;
    float* Ws = Vs + LQ * 65;

    const int id = blockIdx.x;
    const int g = id & 7, h = (id >> 3) & 15, b = id >> 7;
    const int tid = threadIdx.x;
    const int warp = tid >> 5, lane = tid & 31;

    size_t off = (size_t)id * (GT * HS);
    for (int idx = tid; idx < GT * HS; idx += 256) {
        int t = idx >> 6, d = idx & 63;
        Qs[t * 65 + d] = g_q[off + idx];
        Ks[t * 65 + d] = g_k[off + idx];
        Vs[t * 65 + d] = g_v[off + idx];
    }
    if (tid < HS) {
        Qs[256 * 65 + tid] = g_qm[(size_t)id * HS + tid];
        Ks[256 * 65 + tid] = g_km[(size_t)id * HS + tid];
        Vs[256 * 65 + tid] = g_vm[(size_t)id * HS + tid];
    }
    __syncthreads();

    for (int i = warp; i < LQ; i += 8) {
        const float* qp = Qs + i * 65;
        float mx = -1e30f;
        for (int j = lane; j <= i; j += 32) {
            const float* kp = Ks + j * 65;
            float s = 0.f;
#pragma unroll
            for (int dd = 0; dd < HS; dd++) s += qp[dd] * kp[dd];
            s *= 0.125f;
            Ws[warp * LQ + j] = s;
            mx = fmaxf(mx, s);
        }
#pragma unroll
        for (int o = 16; o; o >>= 1) mx = fmaxf(mx, __shfl_xor_sync(0xffffffffu, mx, o));
        float sum = 0.f;
        for (int j = lane; j <= i; j += 32) {
            float e = __expf(Ws[warp * LQ + j] - mx);
            Ws[warp * LQ + j] = e;
            sum += e;
        }
#pragma unroll
        for (int o = 16; o; o >>= 1) sum += __shfl_xor_sync(0xffffffffu, sum, o);
        float inv = 1.f / sum;
        __syncwarp();

        float acc0 = 0.f, acc1 = 0.f;
        for (int j = 0; j <= i; j++) {
            float w = Ws[warp * LQ + j];
            acc0 += w * Vs[j * 65 + lane];
            acc1 += w * Vs[j * 65 + lane + 32];
        }
        acc0 *= inv; acc1 *= inv;

        if (i < GT) {
            size_t o = ((size_t)b * T_ + g * GT + i) * C_ + h * HS;
            g_xo[o + lane]      = tf32r(acc0);
            g_xo[o + lane + 32] = tf32r(acc1);
        } else {
            g_attm[(size_t)id * HS + lane]      = acc0;
            g_attm[(size_t)id * HS + lane + 32] = acc1;
        }
        __syncwarp();
    }
}

// ---------------- level-2 tiny 7x7 causal attention + y outputs ----------------
__global__ void second_kernel(float* __restrict__ out) {
    __shared__ float q7[7][64], k7[7][64], a7[7][64];
    __shared__ float S[7][8], W[7][8];
    const int id = blockIdx.x;
    const int tid = threadIdx.x;

    for (int idx = tid; idx < 7 * 64; idx += 64) {
        int j = idx >> 6, d = idx & 63;
        q7[j][d] = g_qm[((size_t)id * NG + j) * HS + d];
        k7[j][d] = g_km[((size_t)id * NG + j) * HS + d];
        a7[j][d] = g_attm[((size_t)id * NG + j) * HS + d];
    }
    __syncthreads();

    if (tid < 28) {
        int p = tid, j = 0;
        while ((j + 1) * (j + 2) / 2 <= p) j++;
        int jp = p - j * (j + 1) / 2;
        float s = 0.f;
#pragma unroll
        for (int dd = 0; dd < 64; dd++) s += q7[j][dd] * k7[jp][dd];
        S[j][jp] = s * 0.125f;
    }
    __syncthreads();

    if (tid < 7) {
        int j = tid;
        float mx = -1e30f;
        for (int jp = 0; jp <= j; jp++) mx = fmaxf(mx, S[j][jp]);
        float sum = 0.f;
        for (int jp = 0; jp <= j; jp++) { float e = __expf(S[j][jp] - mx); W[j][jp] = e; sum += e; }
        float inv = 1.f / sum;
        for (int jp = 0; jp <= j; jp++) W[j][jp] *= inv;
    }
    __syncthreads();

    const size_t yq_off = (size_t)B_ * T_ * C_;
    const size_t ylen   = (size_t)B_ * NH * 7 * HS;
    int d = tid;
    for (int j = 0; j < 7; j++) {
        float acc = 0.f;
        for (int jp = 0; jp <= j; jp++) acc += W[j][jp] * a7[jp][d];
        size_t o = ((size_t)id * 7 + j) * HS + d;
        out[yq_off            + o] = q7[j][d];
        out[yq_off +     ylen + o] = k7[j][d];
        out[yq_off + 2 * ylen + o] = acc;
    }
}

// ---------------- launch ----------------
extern "C" void kernel_launch(void* const* d_in, const int* in_sizes, int n_in,
                              void* d_out, int out_size) {
    (void)in_sizes; (void)n_in; (void)out_size;
    const float* x      = (const float*)d_in[0];
    const float* W_attn = (const float*)d_in[1];
    const float* W_proj = (const float*)d_in[2];
    float* out = (float*)d_out;

    // pre-round to tf32 (HMMA truncates; round-to-nearest halves the error)
    round_kernel<<<B_*T_*C_/1024, 256>>>(x, 0);
    round_kernel<<<3*C_*C_/1024, 256>>>(W_attn, 1);
    round_kernel<<<C_*C_/1024, 256>>>(W_proj, 2);

    const int gemm_smem = STAGES * STG_FLOATS * (int)sizeof(float);   // 107520
    cudaFuncSetAttribute(gemm_tf32_kernel, cudaFuncAttributeMaxDynamicSharedMemorySize, gemm_smem);

    // qkv = x @ W_attn  (M=16384, N=3072)
    gemm_tf32_kernel<<<dim3(128, 24), 256, gemm_smem>>>(nullptr, 3 * C_, 0);

    means_kernel<<<B_ * NH * NG, 192>>>();

    const int att_smem = (3 * LQ * 65 + 8 * LQ) * (int)sizeof(float);
    cudaFuncSetAttribute(attn_kernel, cudaFuncAttributeMaxDynamicSharedMemorySize, att_smem);
    attn_kernel<<<B_ * NH * NG, 256, att_smem>>>();

    second_kernel<<<B_ * NH, 64>>>(out);

    // out = xo @ W_proj  (M=16384, N=1024)
    gemm_tf32_kernel<<<dim3(128, 8), 256, gemm_smem>>>(out, C_, 1);
}

// round 6
// speedup vs baseline: 1.1487x; 1.1487x over previous
#include <cuda_runtime.h>
#include <cuda_bf16.h>
#include <cstdint>

// Shapes (fixed for this problem)
#define B_  8
#define T_  2048
#define C_  1024
#define NH  16
#define HS  64
#define NG  8
#define GT  256        // tokens per group
#define LQ  257        // GT + 1 mean token

// ---------------- device scratch (no allocations allowed) ----------------
__device__ float g_q[B_*NH*NG*GT*HS];
__device__ float g_k[B_*NH*NG*GT*HS];
__device__ float g_v[B_*NH*NG*GT*HS];
__device__ float g_qm[B_*NH*NG*HS];
__device__ float g_km[B_*NH*NG*HS];
__device__ float g_vm[B_*NH*NG*HS];
__device__ float g_attm[B_*NH*NG*HS];
__device__ float g_xo[B_*T_*C_];          // attn output, tf32-rounded + k-interleaved
__device__ float g_xr[B_*T_*C_];          // x, tf32-rounded + k-interleaved
__device__ float g_War[3*C_*C_];          // W_attn^T [3072][1024], rounded + k-interleaved
__device__ float g_WpR[C_*C_];            // W_proj^T [1024][1024], rounded + k-interleaved

// k-interleave within groups of 8: pairs (k, k+4) adjacent
__device__ __forceinline__ int kperm(int k) {
    return (k & ~7) | ((k & 3) << 1) | ((k >> 2) & 1);
}

// ---------------- helpers ----------------
__device__ __forceinline__ float tf32r(float x) {
    unsigned r;
    asm("cvt.rna.tf32.f32 %0, %1;" : "=r"(r) : "f"(x));
    return __uint_as_float(r);
}

__device__ __forceinline__ uint32_t smem_u32(const void* p) {
    uint32_t a;
    asm("{ .reg .u64 t; cvta.to.shared.u64 t, %1; cvt.u32.u64 %0, t; }" : "=r"(a) : "l"(p));
    return a;
}

__device__ __forceinline__ void cp16(uint32_t dst, const void* src) {
    asm volatile("cp.async.cg.shared.global [%0], [%1], 16;\n" :: "r"(dst), "l"(src));
}
#define CP_COMMIT() asm volatile("cp.async.commit_group;\n" ::: "memory")
#define CP_WAIT(n)  asm volatile("cp.async.wait_group %0;\n" :: "n"(n) : "memory")

__device__ __forceinline__ void mma_tf32(float& c0, float& c1, float& c2, float& c3,
                                         float a0, float a1, float a2, float a3,
                                         float b0, float b1) {
    asm volatile(
        "mma.sync.aligned.m16n8k8.row.col.f32.tf32.tf32.f32 "
        "{%0,%1,%2,%3}, {%4,%5,%6,%7}, {%8,%9}, {%0,%1,%2,%3};\n"
        : "+f"(c0), "+f"(c1), "+f"(c2), "+f"(c3)
        : "r"(__float_as_uint(a0)), "r"(__float_as_uint(a1)),
          "r"(__float_as_uint(a2)), "r"(__float_as_uint(a3)),
          "r"(__float_as_uint(b0)), "r"(__float_as_uint(b1)));
}

// ---------------- pre-round + interleave (A operands) ----------------
// which 0 -> g_xr  (device globals resolved in device code)
__global__ void round_ilv_kernel(const float* __restrict__ src, int which) {
    float* dst = g_xr; (void)which;
    int i = (blockIdx.x * 256 + threadIdx.x) * 8;
    float4 v0 = *reinterpret_cast<const float4*>(src + i);
    float4 v1 = *reinterpret_cast<const float4*>(src + i + 4);
    // out positions: {k0,k4,k1,k5, k2,k6,k3,k7}, rounded
    float4 o0 = make_float4(tf32r(v0.x), tf32r(v1.x), tf32r(v0.y), tf32r(v1.y));
    float4 o1 = make_float4(tf32r(v0.z), tf32r(v1.z), tf32r(v0.w), tf32r(v1.w));
    *reinterpret_cast<float4*>(dst + i)     = o0;
    *reinterpret_cast<float4*>(dst + i + 4) = o1;
}

// W[K=1024][N] row-major -> Wt[N][1024] transposed + rounded + k-interleaved
__global__ void roundT_kernel(const float* __restrict__ W, int N, int which) {
    float* Wt = (which == 1) ? g_War : g_WpR;
    __shared__ float tile[32][33];
    int bx = blockIdx.x * 32;   // n
    int by = blockIdx.y * 32;   // k
    int tx = threadIdx.x & 31, ty = threadIdx.x >> 5;
#pragma unroll
    for (int yy = ty; yy < 32; yy += 8)
        tile[yy][tx] = tf32r(W[(size_t)(by + yy) * N + bx + tx]);
    __syncthreads();
#pragma unroll
    for (int yy = ty; yy < 32; yy += 8) {
        int n = bx + yy, k = by + tx;
        Wt[(size_t)n * 1024 + kperm(k)] = tile[tx][yy];
    }
}

// ---------------- pipelined tf32 GEMM: C[M,N] = A[M,K=1024] @ Wt[N,K]^T ----------------
// smem per stage: A[128][32] then B[128][32], rows rotated by 32B*(row&3)
#define BK 32
#define KCHUNKS 32
#define STAGES 3
#define A_STG_F 4096
#define STG_F   8192               // 32 KB per stage

__global__ __launch_bounds__(256, 2)
void gemm_tf32_kernel(float* __restrict__ Cout, int mode) {
    extern __shared__ float smemf[];
    const uint32_t smem_b = smem_u32(smemf);

    const float* __restrict__ A  = (mode == 0) ? g_xr  : g_xo;
    const float* __restrict__ Bm = (mode == 0) ? g_War : g_WpR;

    const int tid  = threadIdx.x;
    const int warp = tid >> 5;
    const int lane = tid & 31;
    const int wm   = warp & 1;      // 2 warps along M (64 each)
    const int wn   = warp >> 1;     // 4 warps along N (32 each)
    const int bm   = blockIdx.x * 128;
    const int bn   = blockIdx.y * 128;

    float acc[4][4][4];
#pragma unroll
    for (int mt = 0; mt < 4; mt++)
#pragma unroll
        for (int nt = 0; nt < 4; nt++)
#pragma unroll
            for (int i = 0; i < 4; i++) acc[mt][nt][i] = 0.f;

    const int crow = tid >> 1;                     // 0..127
    const int cseg0 = (tid & 1) * 4;               // segs cseg0..cseg0+3
    const int rot = (crow & 3) * 2;

    auto issue_copy = [&](int c, int s) {
        const int k0 = c * BK;
        const uint32_t base = smem_b + (uint32_t)(s * STG_F) * 4u;
        const float* Asrc = A + (size_t)(bm + crow) * 1024 + k0;
        const float* Bsrc = Bm + (size_t)(bn + crow) * 1024 + k0;
#pragma unroll
        for (int u = 0; u < 4; u++) {
            int seg = cseg0 + u;
            int segp = (seg + rot) & 7;
            cp16(base + (uint32_t)(crow * 128 + segp * 16), Asrc + seg * 4);
            cp16(base + (uint32_t)(A_STG_F * 4 + crow * 128 + segp * 16), Bsrc + seg * 4);
        }
        CP_COMMIT();
    };

    issue_copy(0, 0);
    issue_copy(1, 1);

    const int lr  = lane >> 2;        // 0..7
    const int lc  = lane & 3;         // 0..3
    const int g_rot = (lr & 3) << 2;  // row&3 == lr&3 for all tiles here

    int stage = 0;
    for (int c = 0; c < KCHUNKS; c++) {
        if (c + 2 < KCHUNKS) { CP_WAIT(1); } else { CP_WAIT(0); }
        __syncthreads();
        if (c + 2 < KCHUNKS) {
            int ns = stage + 2; if (ns >= STAGES) ns -= STAGES;
            issue_copy(c + 2, ns);
        }

        const float* As = smemf + stage * STG_F;
        const float* Bs = As + A_STG_F;

#pragma unroll
        for (int ks = 0; ks < 4; ks++) {
            const int gidx = (ks * 4 + lc + g_rot) & 15;   // granule within row
            float2 alo[4], ahi[4], bb[4];
#pragma unroll
            for (int mt = 0; mt < 4; mt++) {
                const int row = wm * 64 + mt * 16 + lr;
                alo[mt] = *reinterpret_cast<const float2*>(As + row * 32 + 2 * gidx);
                ahi[mt] = *reinterpret_cast<const float2*>(As + (row + 8) * 32 + 2 * gidx);
            }
#pragma unroll
            for (int nt = 0; nt < 4; nt++) {
                const int ncol = wn * 32 + nt * 8 + lr;
                bb[nt] = *reinterpret_cast<const float2*>(Bs + ncol * 32 + 2 * gidx);
            }
#pragma unroll
            for (int mt = 0; mt < 4; mt++)
#pragma unroll
                for (int nt = 0; nt < 4; nt++)
                    mma_tf32(acc[mt][nt][0], acc[mt][nt][1], acc[mt][nt][2], acc[mt][nt][3],
                             alo[mt].x, ahi[mt].x, alo[mt].y, ahi[mt].y,
                             bb[nt].x, bb[nt].y);
        }
        __syncthreads();
        stage++; if (stage >= STAGES) stage = 0;
    }

    // ---- epilogue: float2 stores ----
    const int N = (mode == 0) ? 3 * C_ : C_;
#pragma unroll
    for (int mt = 0; mt < 4; mt++) {
#pragma unroll
        for (int i2 = 0; i2 < 2; i2++) {
            const int r = bm + wm * 64 + mt * 16 + lr + i2 * 8;
#pragma unroll
            for (int nt = 0; nt < 4; nt++) {
                const int c = bn + wn * 32 + nt * 8 + lc * 2;
                float2 v = make_float2(acc[mt][nt][i2 * 2], acc[mt][nt][i2 * 2 + 1]);
                if (mode == 0) {
                    const int which = c >> 10, cc = c & 1023;
                    const int h = cc >> 6, d0 = cc & 63;
                    const int b = r >> 11, tg = r & 2047, g = tg >> 8, t = tg & 255;
                    float* base = (which == 0) ? g_q : (which == 1) ? g_k : g_v;
                    *reinterpret_cast<float2*>(
                        base + ((((size_t)b * NH + h) * NG + g) * GT + t) * HS + d0) = v;
                } else {
                    *reinterpret_cast<float2*>(Cout + (size_t)r * N + c) = v;
                }
            }
        }
    }
}

// ---------------- group means ----------------
__global__ void means_kernel() {
    int id = blockIdx.x;
    int d = threadIdx.x & 63;
    int which = threadIdx.x >> 6;
    const float* src = (which == 0) ? g_q : (which == 1) ? g_k : g_v;
    float* dst = (which == 0) ? g_qm : (which == 1) ? g_km : g_vm;
    size_t base = (size_t)id * (GT * HS);
    float s = 0.f;
#pragma unroll 8
    for (int t = 0; t < GT; t++) s += src[base + t * HS + d];
    dst[(size_t)id * HS + d] = s * (1.f / 256.f);
}

// ---------------- level-1 causal attention over 257 tokens ----------------
// Qs/Ks: [257][68] (float4-safe), Vt: [64][260] transposed, Ws: [8][260]
#define QK_STRIDE 68
#define VT_STRIDE 260
__global__ __launch_bounds__(256)
void attn_kernel() {
    extern __shared__ float sm[];
    float* Qs = sm;                          // 257*68
    float* Ks = Qs + LQ * QK_STRIDE;         // 257*68
    float* Vt = Ks + LQ * QK_STRIDE;         // 64*260
    float* Ws = Vt + 64 * VT_STRIDE;         // 8*260

    const int id = blockIdx.x;
    const int g = id & 7, h = (id >> 3) & 15, b = id >> 7;
    const int tid = threadIdx.x;
    const int warp = tid >> 5, lane = tid & 31;

    size_t off = (size_t)id * (GT * HS);
    for (int idx = tid; idx < GT * HS; idx += 256) {
        int t = idx >> 6, d = idx & 63;
        Qs[t * QK_STRIDE + d] = g_q[off + idx];
        Ks[t * QK_STRIDE + d] = g_k[off + idx];
        Vt[d * VT_STRIDE + t] = g_v[off + idx];
    }
    if (tid < HS) {
        Qs[256 * QK_STRIDE + tid] = g_qm[(size_t)id * HS + tid];
        Ks[256 * QK_STRIDE + tid] = g_km[(size_t)id * HS + tid];
        Vt[tid * VT_STRIDE + 256] = g_vm[(size_t)id * HS + tid];
        // zero Vt padding cols 257..259 (0*NaN hazard in float4 PV)
        Vt[tid * VT_STRIDE + 257] = 0.f;
        Vt[tid * VT_STRIDE + 258] = 0.f;
        Vt[tid * VT_STRIDE + 259] = 0.f;
    }
    __syncthreads();

    for (int i = warp; i < LQ; i += 8) {
        const float4* qp = reinterpret_cast<const float4*>(Qs + i * QK_STRIDE);
        float mx = -1e30f;
        for (int j = lane; j <= i; j += 32) {
            const float4* kp = reinterpret_cast<const float4*>(Ks + j * QK_STRIDE);
            float s = 0.f;
#pragma unroll
            for (int dd = 0; dd < 16; dd++) {
                float4 qv = qp[dd], kv = kp[dd];
                s += qv.x * kv.x + qv.y * kv.y + qv.z * kv.z + qv.w * kv.w;
            }
            s *= 0.125f;
            Ws[warp * VT_STRIDE + j] = s;
            mx = fmaxf(mx, s);
        }
#pragma unroll
        for (int o = 16; o; o >>= 1) mx = fmaxf(mx, __shfl_xor_sync(0xffffffffu, mx, o));
        float sum = 0.f;
        for (int j = lane; j <= i; j += 32) {
            float e = __expf(Ws[warp * VT_STRIDE + j] - mx);
            Ws[warp * VT_STRIDE + j] = e;
            sum += e;
        }
#pragma unroll
        for (int o = 16; o; o >>= 1) sum += __shfl_xor_sync(0xffffffffu, sum, o);
        float inv = 1.f / sum;
        // zero weight padding up to next multiple of 4
        if (lane < 3) {
            int jz = i + 1 + lane;
            if (jz < ((i + 4) & ~3)) Ws[warp * VT_STRIDE + jz] = 0.f;
        }
        __syncwarp();

        float acc0 = 0.f, acc1 = 0.f;
        const float* wrow = Ws + warp * VT_STRIDE;
        const float* v0p = Vt + lane * VT_STRIDE;
        const float* v1p = Vt + (lane + 32) * VT_STRIDE;
        for (int j = 0; j <= i; j += 4) {
            float4 w  = *reinterpret_cast<const float4*>(wrow + j);
            float4 v0 = *reinterpret_cast<const float4*>(v0p + j);
            float4 v1 = *reinterpret_cast<const float4*>(v1p + j);
            acc0 += w.x * v0.x + w.y * v0.y + w.z * v0.z + w.w * v0.w;
            acc1 += w.x * v1.x + w.y * v1.y + w.z * v1.z + w.w * v1.w;
        }
        acc0 *= inv; acc1 *= inv;

        if (i < GT) {
            // write tf32-rounded, k-interleaved (g_xo is the proj GEMM's A)
            size_t o = ((size_t)b * T_ + g * GT + i) * C_ + h * HS;
            g_xo[o + kperm(lane)]      = tf32r(acc0);
            g_xo[o + kperm(lane + 32)] = tf32r(acc1);
        } else {
            g_attm[(size_t)id * HS + lane]      = acc0;
            g_attm[(size_t)id * HS + lane + 32] = acc1;
        }
        __syncwarp();
    }
}

// ---------------- level-2 tiny 7x7 causal attention + y outputs ----------------
__global__ void second_kernel(float* __restrict__ out) {
    __shared__ float q7[7][64], k7[7][64], a7[7][64];
    __shared__ float S[7][8], W[7][8];
    const int id = blockIdx.x;
    const int tid = threadIdx.x;

    for (int idx = tid; idx < 7 * 64; idx += 64) {
        int j = idx >> 6, d = idx & 63;
        q7[j][d] = g_qm[((size_t)id * NG + j) * HS + d];
        k7[j][d] = g_km[((size_t)id * NG + j) * HS + d];
        a7[j][d] = g_attm[((size_t)id * NG + j) * HS + d];
    }
    __syncthreads();

    if (tid < 28) {
        int p = tid, j = 0;
        while ((j + 1) * (j + 2) / 2 <= p) j++;
        int jp = p - j * (j + 1) / 2;
        float s = 0.f;
#pragma unroll
        for (int dd = 0; dd < 64; dd++) s += q7[j][dd] * k7[jp][dd];
        S[j][jp] = s * 0.125f;
    }
    __syncthreads();

    if (tid < 7) {
        int j = tid;
        float mx = -1e30f;
        for (int jp = 0; jp <= j; jp++) mx = fmaxf(mx, S[j][jp]);
        float sum = 0.f;
        for (int jp = 0; jp <= j; jp++) { float e = __expf(S[j][jp] - mx); W[j][jp] = e; sum += e; }
        float inv = 1.f / sum;
        for (int jp = 0; jp <= j; jp++) W[j][jp] *= inv;
    }
    __syncthreads();

    const size_t yq_off = (size_t)B_ * T_ * C_;
    const size_t ylen   = (size_t)B_ * NH * 7 * HS;
    int d = tid;
    for (int j = 0; j < 7; j++) {
        float acc = 0.f;
        for (int jp = 0; jp <= j; jp++) acc += W[j][jp] * a7[jp][d];
        size_t o = ((size_t)id * 7 + j) * HS + d;
        out[yq_off            + o] = q7[j][d];
        out[yq_off +     ylen + o] = k7[j][d];
        out[yq_off + 2 * ylen + o] = acc;
    }
}

// ---------------- launch ----------------
extern "C" void kernel_launch(void* const* d_in, const int* in_sizes, int n_in,
                              void* d_out, int out_size) {
    (void)in_sizes; (void)n_in; (void)out_size;
    const float* x      = (const float*)d_in[0];
    const float* W_attn = (const float*)d_in[1];
    const float* W_proj = (const float*)d_in[2];
    float* out = (float*)d_out;

    round_ilv_kernel<<<B_*T_*C_/2048, 256>>>(x, 0);
    roundT_kernel<<<dim3(96, 32), 256>>>(W_attn, 3 * C_, 1);
    roundT_kernel<<<dim3(32, 32), 256>>>(W_proj, C_, 2);

    const int gemm_smem = STAGES * STG_F * (int)sizeof(float);   // 98304
    cudaFuncSetAttribute(gemm_tf32_kernel, cudaFuncAttributeMaxDynamicSharedMemorySize, gemm_smem);

    // qkv = x @ W_attn  (M=16384, N=3072)
    gemm_tf32_kernel<<<dim3(128, 24), 256, gemm_smem>>>(nullptr, 0);

    means_kernel<<<B_ * NH * NG, 192>>>();

    const int att_smem = (2 * LQ * QK_STRIDE + 64 * VT_STRIDE + 8 * VT_STRIDE) * (int)sizeof(float);
    cudaFuncSetAttribute(attn_kernel, cudaFuncAttributeMaxDynamicSharedMemorySize, att_smem);
    attn_kernel<<<B_ * NH * NG, 256, att_smem>>>();

    second_kernel<<<B_ * NH, 64>>>(out);

    // out = xo @ W_proj  (M=16384, N=1024)
    gemm_tf32_kernel<<<dim3(128, 8), 256, gemm_smem>>>(out, 1);
}

// round 7
// speedup vs baseline: 1.3541x; 1.1788x over previous
#include <cuda_runtime.h>
#include <cuda_bf16.h>
#include <cstdint>

// Shapes (fixed for this problem)
#define B_  8
#define T_  2048
#define C_  1024
#define NH  16
#define HS  64
#define NG  8
#define GT  256        // tokens per group
#define LQ  257        // GT + 1 mean token

// ---------------- device scratch (no allocations allowed) ----------------
__device__ float g_q[B_*NH*NG*GT*HS];
__device__ float g_k[B_*NH*NG*GT*HS];
__device__ float g_v[B_*NH*NG*GT*HS];
__device__ float g_qm[B_*NH*NG*HS];
__device__ float g_km[B_*NH*NG*HS];
__device__ float g_vm[B_*NH*NG*HS];
__device__ float g_attm[B_*NH*NG*HS];
__device__ float g_xo[B_*T_*C_];          // attn output, tf32-rounded + k-interleaved
__device__ float g_xr[B_*T_*C_];          // x, tf32-rounded + k-interleaved
__device__ float g_War[3*C_*C_];          // W_attn^T [3072][1024], rounded + k-interleaved
__device__ float g_WpR[C_*C_];            // W_proj^T [1024][1024], rounded + k-interleaved

// k-interleave within groups of 8: pairs (k, k+4) adjacent
__device__ __forceinline__ int kperm(int k) {
    return (k & ~7) | ((k & 3) << 1) | ((k >> 2) & 1);
}

// ---------------- helpers ----------------
__device__ __forceinline__ float tf32r(float x) {
    unsigned r;
    asm("cvt.rna.tf32.f32 %0, %1;" : "=r"(r) : "f"(x));
    return __uint_as_float(r);
}

__device__ __forceinline__ uint32_t smem_u32(const void* p) {
    uint32_t a;
    asm("{ .reg .u64 t; cvta.to.shared.u64 t, %1; cvt.u32.u64 %0, t; }" : "=r"(a) : "l"(p));
    return a;
}

__device__ __forceinline__ void cp16(uint32_t dst, const void* src) {
    asm volatile("cp.async.cg.shared.global [%0], [%1], 16;\n" :: "r"(dst), "l"(src));
}
#define CP_COMMIT() asm volatile("cp.async.commit_group;\n" ::: "memory")
#define CP_WAIT(n)  asm volatile("cp.async.wait_group %0;\n" :: "n"(n) : "memory")

__device__ __forceinline__ void mma_tf32(float& c0, float& c1, float& c2, float& c3,
                                         float a0, float a1, float a2, float a3,
                                         float b0, float b1) {
    asm volatile(
        "mma.sync.aligned.m16n8k8.row.col.f32.tf32.tf32.f32 "
        "{%0,%1,%2,%3}, {%4,%5,%6,%7}, {%8,%9}, {%0,%1,%2,%3};\n"
        : "+f"(c0), "+f"(c1), "+f"(c2), "+f"(c3)
        : "r"(__float_as_uint(a0)), "r"(__float_as_uint(a1)),
          "r"(__float_as_uint(a2)), "r"(__float_as_uint(a3)),
          "r"(__float_as_uint(b0)), "r"(__float_as_uint(b1)));
}

// ---------------- pre-round + interleave (A operands) ----------------
__global__ void round_ilv_kernel(const float* __restrict__ src, int which) {
    float* dst = g_xr; (void)which;
    int i = (blockIdx.x * 256 + threadIdx.x) * 8;
    float4 v0 = *reinterpret_cast<const float4*>(src + i);
    float4 v1 = *reinterpret_cast<const float4*>(src + i + 4);
    float4 o0 = make_float4(tf32r(v0.x), tf32r(v1.x), tf32r(v0.y), tf32r(v1.y));
    float4 o1 = make_float4(tf32r(v0.z), tf32r(v1.z), tf32r(v0.w), tf32r(v1.w));
    *reinterpret_cast<float4*>(dst + i)     = o0;
    *reinterpret_cast<float4*>(dst + i + 4) = o1;
}

// W[K=1024][N] row-major -> Wt[N][1024] transposed + rounded + k-interleaved
__global__ void roundT_kernel(const float* __restrict__ W, int N, int which) {
    float* Wt = (which == 1) ? g_War : g_WpR;
    __shared__ float tile[32][33];
    int bx = blockIdx.x * 32;   // n
    int by = blockIdx.y * 32;   // k
    int tx = threadIdx.x & 31, ty = threadIdx.x >> 5;
#pragma unroll
    for (int yy = ty; yy < 32; yy += 8)
        tile[yy][tx] = tf32r(W[(size_t)(by + yy) * N + bx + tx]);
    __syncthreads();
#pragma unroll
    for (int yy = ty; yy < 32; yy += 8) {
        int n = bx + yy, k = by + tx;
        Wt[(size_t)n * 1024 + kperm(k)] = tile[tx][yy];
    }
}

// ---------------- pipelined tf32 GEMM: C[M,N] = A[M,K=1024] @ Wt[N,K]^T ----------------
#define BK 32
#define KCHUNKS 32
#define STAGES 3
#define A_STG_F 4096
#define STG_F   8192               // 32 KB per stage

__global__ __launch_bounds__(256, 2)
void gemm_tf32_kernel(float* __restrict__ Cout, int mode) {
    extern __shared__ float smemf[];
    const uint32_t smem_b = smem_u32(smemf);

    const float* __restrict__ A  = (mode == 0) ? g_xr  : g_xo;
    const float* __restrict__ Bm = (mode == 0) ? g_War : g_WpR;

    const int tid  = threadIdx.x;
    const int warp = tid >> 5;
    const int lane = tid & 31;
    const int wm   = warp & 1;
    const int wn   = warp >> 1;
    const int bm   = blockIdx.x * 128;
    const int bn   = blockIdx.y * 128;

    float acc[4][4][4];
#pragma unroll
    for (int mt = 0; mt < 4; mt++)
#pragma unroll
        for (int nt = 0; nt < 4; nt++)
#pragma unroll
            for (int i = 0; i < 4; i++) acc[mt][nt][i] = 0.f;

    const int crow = tid >> 1;
    const int cseg0 = (tid & 1) * 4;
    const int rot = (crow & 3) * 2;

    auto issue_copy = [&](int c, int s) {
        const int k0 = c * BK;
        const uint32_t base = smem_b + (uint32_t)(s * STG_F) * 4u;
        const float* Asrc = A + (size_t)(bm + crow) * 1024 + k0;
        const float* Bsrc = Bm + (size_t)(bn + crow) * 1024 + k0;
#pragma unroll
        for (int u = 0; u < 4; u++) {
            int seg = cseg0 + u;
            int segp = (seg + rot) & 7;
            cp16(base + (uint32_t)(crow * 128 + segp * 16), Asrc + seg * 4);
            cp16(base + (uint32_t)(A_STG_F * 4 + crow * 128 + segp * 16), Bsrc + seg * 4);
        }
        CP_COMMIT();
    };

    issue_copy(0, 0);
    issue_copy(1, 1);

    const int lr  = lane >> 2;
    const int lc  = lane & 3;
    const int g_rot = (lr & 3) << 2;

    int stage = 0;
    for (int c = 0; c < KCHUNKS; c++) {
        if (c + 2 < KCHUNKS) { CP_WAIT(1); } else { CP_WAIT(0); }
        __syncthreads();
        if (c + 2 < KCHUNKS) {
            int ns = stage + 2; if (ns >= STAGES) ns -= STAGES;
            issue_copy(c + 2, ns);
        }

        const float* As = smemf + stage * STG_F;
        const float* Bs = As + A_STG_F;

#pragma unroll
        for (int ks = 0; ks < 4; ks++) {
            const int gidx = (ks * 4 + lc + g_rot) & 15;
            float2 alo[4], ahi[4], bb[4];
#pragma unroll
            for (int mt = 0; mt < 4; mt++) {
                const int row = wm * 64 + mt * 16 + lr;
                alo[mt] = *reinterpret_cast<const float2*>(As + row * 32 + 2 * gidx);
                ahi[mt] = *reinterpret_cast<const float2*>(As + (row + 8) * 32 + 2 * gidx);
            }
#pragma unroll
            for (int nt = 0; nt < 4; nt++) {
                const int ncol = wn * 32 + nt * 8 + lr;
                bb[nt] = *reinterpret_cast<const float2*>(Bs + ncol * 32 + 2 * gidx);
            }
#pragma unroll
            for (int mt = 0; mt < 4; mt++)
#pragma unroll
                for (int nt = 0; nt < 4; nt++)
                    mma_tf32(acc[mt][nt][0], acc[mt][nt][1], acc[mt][nt][2], acc[mt][nt][3],
                             alo[mt].x, ahi[mt].x, alo[mt].y, ahi[mt].y,
                             bb[nt].x, bb[nt].y);
        }
        __syncthreads();
        stage++; if (stage >= STAGES) stage = 0;
    }

    const int N = (mode == 0) ? 3 * C_ : C_;
#pragma unroll
    for (int mt = 0; mt < 4; mt++) {
#pragma unroll
        for (int i2 = 0; i2 < 2; i2++) {
            const int r = bm + wm * 64 + mt * 16 + lr + i2 * 8;
#pragma unroll
            for (int nt = 0; nt < 4; nt++) {
                const int c = bn + wn * 32 + nt * 8 + lc * 2;
                float2 v = make_float2(acc[mt][nt][i2 * 2], acc[mt][nt][i2 * 2 + 1]);
                if (mode == 0) {
                    const int which = c >> 10, cc = c & 1023;
                    const int h = cc >> 6, d0 = cc & 63;
                    const int b = r >> 11, tg = r & 2047, g = tg >> 8, t = tg & 255;
                    float* base = (which == 0) ? g_q : (which == 1) ? g_k : g_v;
                    *reinterpret_cast<float2*>(
                        base + ((((size_t)b * NH + h) * NG + g) * GT + t) * HS + d0) = v;
                } else {
                    *reinterpret_cast<float2*>(Cout + (size_t)r * N + c) = v;
                }
            }
        }
    }
}

// ---------------- level-1 causal attention over 257 tokens (paired queries) ----------------
// Qs/Ks: [257][68], Vt: [64][260] transposed, Ws: [16][260] (2 rows per warp)
// Also computes group means in-block (means_kernel eliminated).
#define QK_STRIDE 68
#define VT_STRIDE 260
__global__ __launch_bounds__(256)
void attn_kernel() {
    extern __shared__ float sm[];
    float* Qs = sm;                          // 257*68
    float* Ks = Qs + LQ * QK_STRIDE;         // 257*68
    float* Vt = Ks + LQ * QK_STRIDE;         // 64*260
    float* Ws = Vt + 64 * VT_STRIDE;         // 16*260

    const int id = blockIdx.x;
    const int g = id & 7, h = (id >> 3) & 15, b = id >> 7;
    const int tid = threadIdx.x;
    const int warp = tid >> 5, lane = tid & 31;

    size_t off = (size_t)id * (GT * HS);
    for (int idx = tid; idx < GT * HS; idx += 256) {
        int t = idx >> 6, d = idx & 63;
        Qs[t * QK_STRIDE + d] = g_q[off + idx];
        Ks[t * QK_STRIDE + d] = g_k[off + idx];
        Vt[d * VT_STRIDE + t] = g_v[off + idx];
    }
    __syncthreads();

    // ---- in-block group means (token 256) ----
    {
        int which = tid >> 6;        // 0=q, 1=k, 2=v, 3=idle
        int d = tid & 63;
        if (which == 0) {
            float s = 0.f;
#pragma unroll 8
            for (int t = 0; t < GT; t++) s += Qs[t * QK_STRIDE + d];
            float m = s * (1.f / 256.f);
            Qs[256 * QK_STRIDE + d] = m;
            g_qm[(size_t)id * HS + d] = m;
        } else if (which == 1) {
            float s = 0.f;
#pragma unroll 8
            for (int t = 0; t < GT; t++) s += Ks[t * QK_STRIDE + d];
            float m = s * (1.f / 256.f);
            Ks[256 * QK_STRIDE + d] = m;
            g_km[(size_t)id * HS + d] = m;
        } else if (which == 2) {
            float s = 0.f;
            const float* vp = Vt + d * VT_STRIDE;
#pragma unroll 16
            for (int t = 0; t < GT; t += 4) {
                float4 v = *reinterpret_cast<const float4*>(vp + t);
                s += v.x + v.y + v.z + v.w;
            }
            float m = s * (1.f / 256.f);
            Vt[d * VT_STRIDE + 256] = m;
            Vt[d * VT_STRIDE + 257] = 0.f;
            Vt[d * VT_STRIDE + 258] = 0.f;
            Vt[d * VT_STRIDE + 259] = 0.f;
            g_vm[(size_t)id * HS + d] = m;
        }
    }
    __syncthreads();

    // ---- paired causal attention: warp handles queries (2p, 2p+1); p=128 -> (256,256) ----
    float* W0 = Ws + (2 * warp) * VT_STRIDE;
    float* W1 = W0 + VT_STRIDE;

    for (int p = warp; p <= 128; p += 8) {
        const int i0 = (p == 128) ? 256 : 2 * p;
        const int i1 = (p == 128) ? 256 : 2 * p + 1;
        const float4* q0p = reinterpret_cast<const float4*>(Qs + i0 * QK_STRIDE);
        const float4* q1p = reinterpret_cast<const float4*>(Qs + i1 * QK_STRIDE);

        float mx0 = -1e30f, mx1 = -1e30f;
        for (int j = lane; j <= i1; j += 32) {
            const float4* kp = reinterpret_cast<const float4*>(Ks + j * QK_STRIDE);
            float s0 = 0.f, s1 = 0.f;
#pragma unroll
            for (int dd = 0; dd < 16; dd++) {
                float4 kv = kp[dd];
                float4 qv0 = q0p[dd];
                float4 qv1 = q1p[dd];
                s0 += qv0.x * kv.x + qv0.y * kv.y + qv0.z * kv.z + qv0.w * kv.w;
                s1 += qv1.x * kv.x + qv1.y * kv.y + qv1.z * kv.z + qv1.w * kv.w;
            }
            s0 *= 0.125f; s1 *= 0.125f;
            if (j > i0) s0 = -1e30f;
            W0[j] = s0; W1[j] = s1;
            mx0 = fmaxf(mx0, s0); mx1 = fmaxf(mx1, s1);
        }
#pragma unroll
        for (int o = 16; o; o >>= 1) {
            mx0 = fmaxf(mx0, __shfl_xor_sync(0xffffffffu, mx0, o));
            mx1 = fmaxf(mx1, __shfl_xor_sync(0xffffffffu, mx1, o));
        }
        float sum0 = 0.f, sum1 = 0.f;
        for (int j = lane; j <= i1; j += 32) {
            float e0 = __expf(W0[j] - mx0);
            float e1 = __expf(W1[j] - mx1);
            W0[j] = e0; W1[j] = e1;
            sum0 += e0; sum1 += e1;
        }
#pragma unroll
        for (int o = 16; o; o >>= 1) {
            sum0 += __shfl_xor_sync(0xffffffffu, sum0, o);
            sum1 += __shfl_xor_sync(0xffffffffu, sum1, o);
        }
        const float inv0 = 1.f / sum0;
        const float inv1 = 1.f / sum1;
        // zero pad: W0 beyond i0, W1 beyond i1, up to align4(i1+1)
        const int jmax4 = (i1 + 4) & ~3;
        if (lane < 4) {
            int jz = i0 + 1 + lane;
            if (jz < jmax4) W0[jz] = 0.f;
        }
        if (lane < 3) {
            int jz = i1 + 1 + lane;
            if (jz < jmax4) W1[jz] = 0.f;
        }
        __syncwarp();

        float a00 = 0.f, a01 = 0.f, a10 = 0.f, a11 = 0.f;
        const float* v0p = Vt + lane * VT_STRIDE;
        const float* v1p = Vt + (lane + 32) * VT_STRIDE;
        for (int j = 0; j <= i1; j += 4) {
            float4 w0 = *reinterpret_cast<const float4*>(W0 + j);
            float4 w1 = *reinterpret_cast<const float4*>(W1 + j);
            float4 v0 = *reinterpret_cast<const float4*>(v0p + j);
            float4 v1 = *reinterpret_cast<const float4*>(v1p + j);
            a00 += w0.x * v0.x + w0.y * v0.y + w0.z * v0.z + w0.w * v0.w;
            a01 += w0.x * v1.x + w0.y * v1.y + w0.z * v1.z + w0.w * v1.w;
            a10 += w1.x * v0.x + w1.y * v0.y + w1.z * v0.z + w1.w * v0.w;
            a11 += w1.x * v1.x + w1.y * v1.y + w1.z * v1.z + w1.w * v1.w;
        }
        a00 *= inv0; a01 *= inv0; a10 *= inv1; a11 *= inv1;

        if (i0 < GT) {
            size_t o = ((size_t)b * T_ + g * GT + i0) * C_ + h * HS;
            g_xo[o + kperm(lane)]      = tf32r(a00);
            g_xo[o + kperm(lane + 32)] = tf32r(a01);
        } else {
            g_attm[(size_t)id * HS + lane]      = a00;
            g_attm[(size_t)id * HS + lane + 32] = a01;
        }
        if (i1 < GT) {
            size_t o = ((size_t)b * T_ + g * GT + i1) * C_ + h * HS;
            g_xo[o + kperm(lane)]      = tf32r(a10);
            g_xo[o + kperm(lane + 32)] = tf32r(a11);
        } else {
            g_attm[(size_t)id * HS + lane]      = a10;
            g_attm[(size_t)id * HS + lane + 32] = a11;
        }
        __syncwarp();
    }
}

// ---------------- level-2 tiny 7x7 causal attention + y outputs ----------------
__global__ void second_kernel(float* __restrict__ out) {
    __shared__ float q7[7][64], k7[7][64], a7[7][64];
    __shared__ float S[7][8], W[7][8];
    const int id = blockIdx.x;
    const int tid = threadIdx.x;

    for (int idx = tid; idx < 7 * 64; idx += 64) {
        int j = idx >> 6, d = idx & 63;
        q7[j][d] = g_qm[((size_t)id * NG + j) * HS + d];
        k7[j][d] = g_km[((size_t)id * NG + j) * HS + d];
        a7[j][d] = g_attm[((size_t)id * NG + j) * HS + d];
    }
    __syncthreads();

    if (tid < 28) {
        int p = tid, j = 0;
        while ((j + 1) * (j + 2) / 2 <= p) j++;
        int jp = p - j * (j + 1) / 2;
        float s = 0.f;
#pragma unroll
        for (int dd = 0; dd < 64; dd++) s += q7[j][dd] * k7[jp][dd];
        S[j][jp] = s * 0.125f;
    }
    __syncthreads();

    if (tid < 7) {
        int j = tid;
        float mx = -1e30f;
        for (int jp = 0; jp <= j; jp++) mx = fmaxf(mx, S[j][jp]);
        float sum = 0.f;
        for (int jp = 0; jp <= j; jp++) { float e = __expf(S[j][jp] - mx); W[j][jp] = e; sum += e; }
        float inv = 1.f / sum;
        for (int jp = 0; jp <= j; jp++) W[j][jp] *= inv;
    }
    __syncthreads();

    const size_t yq_off = (size_t)B_ * T_ * C_;
    const size_t ylen   = (size_t)B_ * NH * 7 * HS;
    int d = tid;
    for (int j = 0; j < 7; j++) {
        float acc = 0.f;
        for (int jp = 0; jp <= j; jp++) acc += W[j][jp] * a7[jp][d];
        size_t o = ((size_t)id * 7 + j) * HS + d;
        out[yq_off            + o] = q7[j][d];
        out[yq_off +     ylen + o] = k7[j][d];
        out[yq_off + 2 * ylen + o] = acc;
    }
}

// ---------------- launch ----------------
extern "C" void kernel_launch(void* const* d_in, const int* in_sizes, int n_in,
                              void* d_out, int out_size) {
    (void)in_sizes; (void)n_in; (void)out_size;
    const float* x      = (const float*)d_in[0];
    const float* W_attn = (const float*)d_in[1];
    const float* W_proj = (const float*)d_in[2];
    float* out = (float*)d_out;

    round_ilv_kernel<<<B_*T_*C_/2048, 256>>>(x, 0);
    roundT_kernel<<<dim3(96, 32), 256>>>(W_attn, 3 * C_, 1);
    roundT_kernel<<<dim3(32, 32), 256>>>(W_proj, C_, 2);

    const int gemm_smem = STAGES * STG_F * (int)sizeof(float);   // 98304
    cudaFuncSetAttribute(gemm_tf32_kernel, cudaFuncAttributeMaxDynamicSharedMemorySize, gemm_smem);

    // qkv = x @ W_attn  (M=16384, N=3072)
    gemm_tf32_kernel<<<dim3(128, 24), 256, gemm_smem>>>(nullptr, 0);

    const int att_smem = (2 * LQ * QK_STRIDE + 64 * VT_STRIDE + 16 * VT_STRIDE) * (int)sizeof(float);
    cudaFuncSetAttribute(attn_kernel, cudaFuncAttributeMaxDynamicSharedMemorySize, att_smem);
    attn_kernel<<<B_ * NH * NG, 256, att_smem>>>();

    second_kernel<<<B_ * NH, 64>>>(out);

    // out = xo @ W_proj  (M=16384, N=1024)
    gemm_tf32_kernel<<<dim3(128, 8), 256, gemm_smem>>>(out, 1);
}

// round 8
// speedup vs baseline: 1.3790x; 1.0184x over previous
#include <cuda_runtime.h>
#include <cuda_bf16.h>
#include <cstdint>

// Shapes (fixed for this problem)
#define B_  8
#define T_  2048
#define C_  1024
#define NH  16
#define HS  64
#define NG  8
#define GT  256        // tokens per group
#define LQ  257        // GT + 1 mean token

// ---------------- device scratch (no allocations allowed) ----------------
__device__ float g_q[B_*NH*NG*GT*HS];
__device__ float g_k[B_*NH*NG*GT*HS];
__device__ float g_v[B_*NH*NG*GT*HS];
__device__ float g_qm[B_*NH*NG*HS];
__device__ float g_km[B_*NH*NG*HS];
__device__ float g_vm[B_*NH*NG*HS];
__device__ float g_attm[B_*NH*NG*HS];
__device__ float g_xo[B_*T_*C_];          // attn output, tf32-rounded + k-interleaved
__device__ float g_xr[B_*T_*C_];          // x, tf32-rounded + k-interleaved
__device__ float g_War[3*C_*C_];          // W_attn^T [3072][1024], rounded + k-interleaved
__device__ float g_WpR[C_*C_];            // W_proj^T [1024][1024], rounded + k-interleaved

// k-interleave within groups of 8: pairs (k, k+4) adjacent
__device__ __forceinline__ int kperm(int k) {
    return (k & ~7) | ((k & 3) << 1) | ((k >> 2) & 1);
}

// ---------------- helpers ----------------
__device__ __forceinline__ float tf32r(float x) {
    unsigned r;
    asm("cvt.rna.tf32.f32 %0, %1;" : "=r"(r) : "f"(x));
    return __uint_as_float(r);
}

__device__ __forceinline__ uint32_t smem_u32(const void* p) {
    uint32_t a;
    asm("{ .reg .u64 t; cvta.to.shared.u64 t, %1; cvt.u32.u64 %0, t; }" : "=r"(a) : "l"(p));
    return a;
}

__device__ __forceinline__ void cp16(uint32_t dst, const void* src) {
    asm volatile("cp.async.cg.shared.global [%0], [%1], 16;\n" :: "r"(dst), "l"(src));
}
#define CP_COMMIT() asm volatile("cp.async.commit_group;\n" ::: "memory")
#define CP_WAIT(n)  asm volatile("cp.async.wait_group %0;\n" :: "n"(n) : "memory")

__device__ __forceinline__ void mma_tf32(float& c0, float& c1, float& c2, float& c3,
                                         float a0, float a1, float a2, float a3,
                                         float b0, float b1) {
    asm volatile(
        "mma.sync.aligned.m16n8k8.row.col.f32.tf32.tf32.f32 "
        "{%0,%1,%2,%3}, {%4,%5,%6,%7}, {%8,%9}, {%0,%1,%2,%3};\n"
        : "+f"(c0), "+f"(c1), "+f"(c2), "+f"(c3)
        : "r"(__float_as_uint(a0)), "r"(__float_as_uint(a1)),
          "r"(__float_as_uint(a2)), "r"(__float_as_uint(a3)),
          "r"(__float_as_uint(b0)), "r"(__float_as_uint(b1)));
}

// ---------------- pre-round + interleave (A operands) ----------------
__global__ void round_ilv_kernel(const float* __restrict__ src, int which) {
    float* dst = g_xr; (void)which;
    int i = (blockIdx.x * 256 + threadIdx.x) * 8;
    float4 v0 = *reinterpret_cast<const float4*>(src + i);
    float4 v1 = *reinterpret_cast<const float4*>(src + i + 4);
    float4 o0 = make_float4(tf32r(v0.x), tf32r(v1.x), tf32r(v0.y), tf32r(v1.y));
    float4 o1 = make_float4(tf32r(v0.z), tf32r(v1.z), tf32r(v0.w), tf32r(v1.w));
    *reinterpret_cast<float4*>(dst + i)     = o0;
    *reinterpret_cast<float4*>(dst + i + 4) = o1;
}

// W[K=1024][N] row-major -> Wt[N][1024] transposed + rounded + k-interleaved
__global__ void roundT_kernel(const float* __restrict__ W, int N, int which) {
    float* Wt = (which == 1) ? g_War : g_WpR;
    __shared__ float tile[32][33];
    int bx = blockIdx.x * 32;   // n
    int by = blockIdx.y * 32;   // k
    int tx = threadIdx.x & 31, ty = threadIdx.x >> 5;
#pragma unroll
    for (int yy = ty; yy < 32; yy += 8)
        tile[yy][tx] = tf32r(W[(size_t)(by + yy) * N + bx + tx]);
    __syncthreads();
#pragma unroll
    for (int yy = ty; yy < 32; yy += 8) {
        int n = bx + yy, k = by + tx;
        Wt[(size_t)n * 1024 + kperm(k)] = tile[tx][yy];
    }
}

// ---------------- pipelined tf32 GEMM: C[M,N] = A[M,K=1024] @ Wt[N,K]^T ----------------
#define BK 32
#define KCHUNKS 32
#define STAGES 3
#define A_STG_F 4096
#define STG_F   8192               // 32 KB per stage

__global__ __launch_bounds__(256, 2)
void gemm_tf32_kernel(float* __restrict__ Cout, int mode) {
    extern __shared__ float smemf[];
    const uint32_t smem_b = smem_u32(smemf);

    const float* __restrict__ A  = (mode == 0) ? g_xr  : g_xo;
    const float* __restrict__ Bm = (mode == 0) ? g_War : g_WpR;

    const int tid  = threadIdx.x;
    const int warp = tid >> 5;
    const int lane = tid & 31;
    const int wm   = warp & 1;
    const int wn   = warp >> 1;
    const int bm   = blockIdx.x * 128;
    const int bn   = blockIdx.y * 128;

    float acc[4][4][4];
#pragma unroll
    for (int mt = 0; mt < 4; mt++)
#pragma unroll
        for (int nt = 0; nt < 4; nt++)
#pragma unroll
            for (int i = 0; i < 4; i++) acc[mt][nt][i] = 0.f;

    const int crow = tid >> 1;
    const int cseg0 = (tid & 1) * 4;
    const int rot = (crow & 3) * 2;

    auto issue_copy = [&](int c, int s) {
        const int k0 = c * BK;
        const uint32_t base = smem_b + (uint32_t)(s * STG_F) * 4u;
        const float* Asrc = A + (size_t)(bm + crow) * 1024 + k0;
        const float* Bsrc = Bm + (size_t)(bn + crow) * 1024 + k0;
#pragma unroll
        for (int u = 0; u < 4; u++) {
            int seg = cseg0 + u;
            int segp = (seg + rot) & 7;
            cp16(base + (uint32_t)(crow * 128 + segp * 16), Asrc + seg * 4);
            cp16(base + (uint32_t)(A_STG_F * 4 + crow * 128 + segp * 16), Bsrc + seg * 4);
        }
        CP_COMMIT();
    };

    issue_copy(0, 0);
    issue_copy(1, 1);

    const int lr  = lane >> 2;
    const int lc  = lane & 3;
    const int g_rot = (lr & 3) << 2;

    // fragment rows fixed per thread
    int arow[4], bcol[4];
#pragma unroll
    for (int mt = 0; mt < 4; mt++) arow[mt] = wm * 64 + mt * 16 + lr;
#pragma unroll
    for (int nt = 0; nt < 4; nt++) bcol[nt] = wn * 32 + nt * 8 + lr;

    int stage = 0;
    for (int c = 0; c < KCHUNKS; c++) {
        if (c + 2 < KCHUNKS) { CP_WAIT(1); } else { CP_WAIT(0); }
        __syncthreads();

        const float* As = smemf + stage * STG_F;
        const float* Bs = As + A_STG_F;

        // double-buffered fragments: load ks+1 while MMA-ing ks
        float2 alo[2][4], ahi[2][4], bb[2][4];

        {   // preload ks = 0
            const int gidx = (lc + g_rot) & 15;
#pragma unroll
            for (int mt = 0; mt < 4; mt++) {
                alo[0][mt] = *reinterpret_cast<const float2*>(As + arow[mt] * 32 + 2 * gidx);
                ahi[0][mt] = *reinterpret_cast<const float2*>(As + (arow[mt] + 8) * 32 + 2 * gidx);
            }
#pragma unroll
            for (int nt = 0; nt < 4; nt++)
                bb[0][nt] = *reinterpret_cast<const float2*>(Bs + bcol[nt] * 32 + 2 * gidx);
        }

#pragma unroll
        for (int ks = 0; ks < 4; ks++) {
            const int cur = ks & 1;
            const int nxt = cur ^ 1;
            if (ks < 3) {
                const int gidx = ((ks + 1) * 4 + lc + g_rot) & 15;
#pragma unroll
                for (int mt = 0; mt < 4; mt++) {
                    alo[nxt][mt] = *reinterpret_cast<const float2*>(As + arow[mt] * 32 + 2 * gidx);
                    ahi[nxt][mt] = *reinterpret_cast<const float2*>(As + (arow[mt] + 8) * 32 + 2 * gidx);
                }
#pragma unroll
                for (int nt = 0; nt < 4; nt++)
                    bb[nxt][nt] = *reinterpret_cast<const float2*>(Bs + bcol[nt] * 32 + 2 * gidx);
            }
#pragma unroll
            for (int mt = 0; mt < 4; mt++)
#pragma unroll
                for (int nt = 0; nt < 4; nt++)
                    mma_tf32(acc[mt][nt][0], acc[mt][nt][1], acc[mt][nt][2], acc[mt][nt][3],
                             alo[cur][mt].x, ahi[cur][mt].x, alo[cur][mt].y, ahi[cur][mt].y,
                             bb[cur][nt].x, bb[cur][nt].y);
        }

        // issue next-next chunk copy AFTER compute: the top-of-loop sync already
        // guarantees all warps finished chunk c-1 (whose stage this overwrites).
        if (c + 2 < KCHUNKS) {
            int ns = stage + 2; if (ns >= STAGES) ns -= STAGES;
            issue_copy(c + 2, ns);
        }
        stage++; if (stage >= STAGES) stage = 0;
    }

    const int N = (mode == 0) ? 3 * C_ : C_;
#pragma unroll
    for (int mt = 0; mt < 4; mt++) {
#pragma unroll
        for (int i2 = 0; i2 < 2; i2++) {
            const int r = bm + wm * 64 + mt * 16 + lr + i2 * 8;
#pragma unroll
            for (int nt = 0; nt < 4; nt++) {
                const int c = bn + wn * 32 + nt * 8 + lc * 2;
                float2 v = make_float2(acc[mt][nt][i2 * 2], acc[mt][nt][i2 * 2 + 1]);
                if (mode == 0) {
                    const int which = c >> 10, cc = c & 1023;
                    const int h = cc >> 6, d0 = cc & 63;
                    const int b = r >> 11, tg = r & 2047, g = tg >> 8, t = tg & 255;
                    float* base = (which == 0) ? g_q : (which == 1) ? g_k : g_v;
                    *reinterpret_cast<float2*>(
                        base + ((((size_t)b * NH + h) * NG + g) * GT + t) * HS + d0) = v;
                } else {
                    *reinterpret_cast<float2*>(Cout + (size_t)r * N + c) = v;
                }
            }
        }
    }
}

// ---------------- level-1 causal attention over 257 tokens (paired queries) ----------------
#define QK_STRIDE 68
#define VT_STRIDE 260
__global__ __launch_bounds__(256)
void attn_kernel() {
    extern __shared__ float sm[];
    float* Qs = sm;                          // 257*68
    float* Ks = Qs + LQ * QK_STRIDE;         // 257*68
    float* Vt = Ks + LQ * QK_STRIDE;         // 64*260
    float* Ws = Vt + 64 * VT_STRIDE;         // 16*260

    const int id = blockIdx.x;
    const int g = id & 7, h = (id >> 3) & 15, b = id >> 7;
    const int tid = threadIdx.x;
    const int warp = tid >> 5, lane = tid & 31;

    size_t off = (size_t)id * (GT * HS);
    for (int idx = tid; idx < GT * HS; idx += 256) {
        int t = idx >> 6, d = idx & 63;
        Qs[t * QK_STRIDE + d] = g_q[off + idx];
        Ks[t * QK_STRIDE + d] = g_k[off + idx];
        Vt[d * VT_STRIDE + t] = g_v[off + idx];
    }
    __syncthreads();

    // ---- in-block group means (token 256) ----
    {
        int which = tid >> 6;        // 0=q, 1=k, 2=v, 3=idle
        int d = tid & 63;
        if (which == 0) {
            float s = 0.f;
#pragma unroll 8
            for (int t = 0; t < GT; t++) s += Qs[t * QK_STRIDE + d];
            float m = s * (1.f / 256.f);
            Qs[256 * QK_STRIDE + d] = m;
            g_qm[(size_t)id * HS + d] = m;
        } else if (which == 1) {
            float s = 0.f;
#pragma unroll 8
            for (int t = 0; t < GT; t++) s += Ks[t * QK_STRIDE + d];
            float m = s * (1.f / 256.f);
            Ks[256 * QK_STRIDE + d] = m;
            g_km[(size_t)id * HS + d] = m;
        } else if (which == 2) {
            float s = 0.f;
            const float* vp = Vt + d * VT_STRIDE;
#pragma unroll 16
            for (int t = 0; t < GT; t += 4) {
                float4 v = *reinterpret_cast<const float4*>(vp + t);
                s += v.x + v.y + v.z + v.w;
            }
            float m = s * (1.f / 256.f);
            Vt[d * VT_STRIDE + 256] = m;
            Vt[d * VT_STRIDE + 257] = 0.f;
            Vt[d * VT_STRIDE + 258] = 0.f;
            Vt[d * VT_STRIDE + 259] = 0.f;
            g_vm[(size_t)id * HS + d] = m;
        }
    }
    __syncthreads();

    float* W0 = Ws + (2 * warp) * VT_STRIDE;
    float* W1 = W0 + VT_STRIDE;

    for (int p = warp; p <= 128; p += 8) {
        const int i0 = (p == 128) ? 256 : 2 * p;
        const int i1 = (p == 128) ? 256 : 2 * p + 1;
        const float4* q0p = reinterpret_cast<const float4*>(Qs + i0 * QK_STRIDE);
        const float4* q1p = reinterpret_cast<const float4*>(Qs + i1 * QK_STRIDE);

        float mx0 = -1e30f, mx1 = -1e30f;
        for (int j = lane; j <= i1; j += 32) {
            const float4* kp = reinterpret_cast<const float4*>(Ks + j * QK_STRIDE);
            float s0 = 0.f, s1 = 0.f;
#pragma unroll
            for (int dd = 0; dd < 16; dd++) {
                float4 kv = kp[dd];
                float4 qv0 = q0p[dd];
                float4 qv1 = q1p[dd];
                s0 += qv0.x * kv.x + qv0.y * kv.y + qv0.z * kv.z + qv0.w * kv.w;
                s1 += qv1.x * kv.x + qv1.y * kv.y + qv1.z * kv.z + qv1.w * kv.w;
            }
            s0 *= 0.125f; s1 *= 0.125f;
            if (j > i0) s0 = -1e30f;
            W0[j] = s0; W1[j] = s1;
            mx0 = fmaxf(mx0, s0); mx1 = fmaxf(mx1, s1);
        }
#pragma unroll
        for (int o = 16; o; o >>= 1) {
            mx0 = fmaxf(mx0, __shfl_xor_sync(0xffffffffu, mx0, o));
            mx1 = fmaxf(mx1, __shfl_xor_sync(0xffffffffu, mx1, o));
        }
        float sum0 = 0.f, sum1 = 0.f;
        for (int j = lane; j <= i1; j += 32) {
            float e0 = __expf(W0[j] - mx0);
            float e1 = __expf(W1[j] - mx1);
            W0[j] = e0; W1[j] = e1;
            sum0 += e0; sum1 += e1;
        }
#pragma unroll
        for (int o = 16; o; o >>= 1) {
            sum0 += __shfl_xor_sync(0xffffffffu, sum0, o);
            sum1 += __shfl_xor_sync(0xffffffffu, sum1, o);
        }
        const float inv0 = 1.f / sum0;
        const float inv1 = 1.f / sum1;
        const int jmax4 = (i1 + 4) & ~3;
        if (lane < 4) {
            int jz = i0 + 1 + lane;
            if (jz < jmax4) W0[jz] = 0.f;
        }
        if (lane < 3) {
            int jz = i1 + 1 + lane;
            if (jz < jmax4) W1[jz] = 0.f;
        }
        __syncwarp();

        float a00 = 0.f, a01 = 0.f, a10 = 0.f, a11 = 0.f;
        const float* v0p = Vt + lane * VT_STRIDE;
        const float* v1p = Vt + (lane + 32) * VT_STRIDE;
        for (int j = 0; j <= i1; j += 4) {
            float4 w0 = *reinterpret_cast<const float4*>(W0 + j);
            float4 w1 = *reinterpret_cast<const float4*>(W1 + j);
            float4 v0 = *reinterpret_cast<const float4*>(v0p + j);
            float4 v1 = *reinterpret_cast<const float4*>(v1p + j);
            a00 += w0.x * v0.x + w0.y * v0.y + w0.z * v0.z + w0.w * v0.w;
            a01 += w0.x * v1.x + w0.y * v1.y + w0.z * v1.z + w0.w * v1.w;
            a10 += w1.x * v0.x + w1.y * v0.y + w1.z * v0.z + w1.w * v0.w;
            a11 += w1.x * v1.x + w1.y * v1.y + w1.z * v1.z + w1.w * v1.w;
        }
        a00 *= inv0; a01 *= inv0; a10 *= inv1; a11 *= inv1;

        if (i0 < GT) {
            size_t o = ((size_t)b * T_ + g * GT + i0) * C_ + h * HS;
            g_xo[o + kperm(lane)]      = tf32r(a00);
            g_xo[o + kperm(lane + 32)] = tf32r(a01);
        } else {
            g_attm[(size_t)id * HS + lane]      = a00;
            g_attm[(size_t)id * HS + lane + 32] = a01;
        }
        if (i1 < GT) {
            size_t o = ((size_t)b * T_ + g * GT + i1) * C_ + h * HS;
            g_xo[o + kperm(lane)]      = tf32r(a10);
            g_xo[o + kperm(lane + 32)] = tf32r(a11);
        } else {
            g_attm[(size_t)id * HS + lane]      = a10;
            g_attm[(size_t)id * HS + lane + 32] = a11;
        }
        __syncwarp();
    }
}

// ---------------- level-2 tiny 7x7 causal attention + y outputs ----------------
__global__ void second_kernel(float* __restrict__ out) {
    __shared__ float q7[7][64], k7[7][64], a7[7][64];
    __shared__ float S[7][8], W[7][8];
    const int id = blockIdx.x;
    const int tid = threadIdx.x;

    for (int idx = tid; idx < 7 * 64; idx += 64) {
        int j = idx >> 6, d = idx & 63;
        q7[j][d] = g_qm[((size_t)id * NG + j) * HS + d];
        k7[j][d] = g_km[((size_t)id * NG + j) * HS + d];
        a7[j][d] = g_attm[((size_t)id * NG + j) * HS + d];
    }
    __syncthreads();

    if (tid < 28) {
        int p = tid, j = 0;
        while ((j + 1) * (j + 2) / 2 <= p) j++;
        int jp = p - j * (j + 1) / 2;
        float s = 0.f;
#pragma unroll
        for (int dd = 0; dd < 64; dd++) s += q7[j][dd] * k7[jp][dd];
        S[j][jp] = s * 0.125f;
    }
    __syncthreads();

    if (tid < 7) {
        int j = tid;
        float mx = -1e30f;
        for (int jp = 0; jp <= j; jp++) mx = fmaxf(mx, S[j][jp]);
        float sum = 0.f;
        for (int jp = 0; jp <= j; jp++) { float e = __expf(S[j][jp] - mx); W[j][jp] = e; sum += e; }
        float inv = 1.f / sum;
        for (int jp = 0; jp <= j; jp++) W[j][jp] *= inv;
    }
    __syncthreads();

    const size_t yq_off = (size_t)B_ * T_ * C_;
    const size_t ylen   = (size_t)B_ * NH * 7 * HS;
    int d = tid;
    for (int j = 0; j < 7; j++) {
        float acc = 0.f;
        for (int jp = 0; jp <= j; jp++) acc += W[j][jp] * a7[jp][d];
        size_t o = ((size_t)id * 7 + j) * HS + d;
        out[yq_off            + o] = q7[j][d];
        out[yq_off +     ylen + o] = k7[j][d];
        out[yq_off + 2 * ylen + o] = acc;
    }
}

// ---------------- launch ----------------
extern "C" void kernel_launch(void* const* d_in, const int* in_sizes, int n_in,
                              void* d_out, int out_size) {
    (void)in_sizes; (void)n_in; (void)out_size;
    const float* x      = (const float*)d_in[0];
    const float* W_attn = (const float*)d_in[1];
    const float* W_proj = (const float*)d_in[2];
    float* out = (float*)d_out;

    round_ilv_kernel<<<B_*T_*C_/2048, 256>>>(x, 0);
    roundT_kernel<<<dim3(96, 32), 256>>>(W_attn, 3 * C_, 1);
    roundT_kernel<<<dim3(32, 32), 256>>>(W_proj, C_, 2);

    const int gemm_smem = STAGES * STG_F * (int)sizeof(float);   // 98304
    cudaFuncSetAttribute(gemm_tf32_kernel, cudaFuncAttributeMaxDynamicSharedMemorySize, gemm_smem);

    // qkv = x @ W_attn  (M=16384, N=3072)
    gemm_tf32_kernel<<<dim3(128, 24), 256, gemm_smem>>>(nullptr, 0);

    const int att_smem = (2 * LQ * QK_STRIDE + 64 * VT_STRIDE + 16 * VT_STRIDE) * (int)sizeof(float);
    cudaFuncSetAttribute(attn_kernel, cudaFuncAttributeMaxDynamicSharedMemorySize, att_smem);
    attn_kernel<<<B_ * NH * NG, 256, att_smem>>>();

    second_kernel<<<B_ * NH, 64>>>(out);

    // out = xo @ W_proj  (M=16384, N=1024)
    gemm_tf32_kernel<<<dim3(128, 8), 256, gemm_smem>>>(out, 1);
}

// round 9
// speedup vs baseline: 1.8096x; 1.3123x over previous
#include <cuda_runtime.h>
#include <cuda_bf16.h>
#include <cstdint>

#define B_  8
#define T_  2048
#define C_  1024
#define NH  16
#define HS  64
#define NG  8
#define GT  256
#define LQ  257

// ---------------- device scratch ----------------
__device__ float g_q[B_*NH*NG*GT*HS];
__device__ float g_k[B_*NH*NG*GT*HS];
__device__ float g_v[B_*NH*NG*GT*HS];
__device__ float g_qm[B_*NH*NG*HS];
__device__ float g_km[B_*NH*NG*HS];
__device__ float g_vm[B_*NH*NG*HS];
__device__ float g_attm[B_*NH*NG*HS];
__device__ float g_xo[B_*T_*C_];          // attn out, tf32 + k-interleaved
__device__ float g_xr[B_*T_*C_];
__device__ float g_War[3*C_*C_];
__device__ float g_WpR[C_*C_];

// interleave within groups of 8: pairs (k, k+4) adjacent
__device__ __forceinline__ int perm8(int k)  { return ((k & 3) << 1) | ((k >> 2) & 1); }
__device__ __forceinline__ int inv8(int p)   { return ((p >> 1) & 3) | ((p & 1) << 2); }
__device__ __forceinline__ int kperm(int k)  { return (k & ~7) | perm8(k & 7); }

__device__ __forceinline__ float tf32r(float x) {
    unsigned r;
    asm("cvt.rna.tf32.f32 %0, %1;" : "=r"(r) : "f"(x));
    return __uint_as_float(r);
}

__device__ __forceinline__ uint32_t smem_u32(const void* p) {
    uint32_t a;
    asm("{ .reg .u64 t; cvta.to.shared.u64 t, %1; cvt.u32.u64 %0, t; }" : "=r"(a) : "l"(p));
    return a;
}

__device__ __forceinline__ void cp16(uint32_t dst, const void* src) {
    asm volatile("cp.async.cg.shared.global [%0], [%1], 16;\n" :: "r"(dst), "l"(src));
}
#define CP_COMMIT() asm volatile("cp.async.commit_group;\n" ::: "memory")
#define CP_WAIT(n)  asm volatile("cp.async.wait_group %0;\n" :: "n"(n) : "memory")

__device__ __forceinline__ void mma_tf32(float& c0, float& c1, float& c2, float& c3,
                                         float a0, float a1, float a2, float a3,
                                         float b0, float b1) {
    asm volatile(
        "mma.sync.aligned.m16n8k8.row.col.f32.tf32.tf32.f32 "
        "{%0,%1,%2,%3}, {%4,%5,%6,%7}, {%8,%9}, {%0,%1,%2,%3};\n"
        : "+f"(c0), "+f"(c1), "+f"(c2), "+f"(c3)
        : "r"(__float_as_uint(a0)), "r"(__float_as_uint(a1)),
          "r"(__float_as_uint(a2)), "r"(__float_as_uint(a3)),
          "r"(__float_as_uint(b0)), "r"(__float_as_uint(b1)));
}

// ---------------- pre-round kernels ----------------
__global__ void round_ilv_kernel(const float* __restrict__ src, int which) {
    float* dst = g_xr; (void)which;
    int i = (blockIdx.x * 256 + threadIdx.x) * 8;
    float4 v0 = *reinterpret_cast<const float4*>(src + i);
    float4 v1 = *reinterpret_cast<const float4*>(src + i + 4);
    float4 o0 = make_float4(tf32r(v0.x), tf32r(v1.x), tf32r(v0.y), tf32r(v1.y));
    float4 o1 = make_float4(tf32r(v0.z), tf32r(v1.z), tf32r(v0.w), tf32r(v1.w));
    *reinterpret_cast<float4*>(dst + i)     = o0;
    *reinterpret_cast<float4*>(dst + i + 4) = o1;
}

__global__ void roundT_kernel(const float* __restrict__ W, int N, int which) {
    float* Wt = (which == 1) ? g_War : g_WpR;
    __shared__ float tile[32][33];
    int bx = blockIdx.x * 32;
    int by = blockIdx.y * 32;
    int tx = threadIdx.x & 31, ty = threadIdx.x >> 5;
#pragma unroll
    for (int yy = ty; yy < 32; yy += 8)
        tile[yy][tx] = tf32r(W[(size_t)(by + yy) * N + bx + tx]);
    __syncthreads();
#pragma unroll
    for (int yy = ty; yy < 32; yy += 8) {
        int n = bx + yy, k = by + tx;
        Wt[(size_t)n * 1024 + kperm(k)] = tile[tx][yy];
    }
}

// ---------------- pipelined tf32 GEMM (unchanged from round 8) ----------------
#define BK 32
#define KCHUNKS 32
#define STAGES 3
#define A_STG_F 4096
#define STG_F   8192

__global__ __launch_bounds__(256, 2)
void gemm_tf32_kernel(float* __restrict__ Cout, int mode) {
    extern __shared__ float smemf[];
    const uint32_t smem_b = smem_u32(smemf);

    const float* __restrict__ A  = (mode == 0) ? g_xr  : g_xo;
    const float* __restrict__ Bm = (mode == 0) ? g_War : g_WpR;

    const int tid  = threadIdx.x;
    const int warp = tid >> 5;
    const int lane = tid & 31;
    const int wm   = warp & 1;
    const int wn   = warp >> 1;
    const int bm   = blockIdx.x * 128;
    const int bn   = blockIdx.y * 128;

    float acc[4][4][4];
#pragma unroll
    for (int mt = 0; mt < 4; mt++)
#pragma unroll
        for (int nt = 0; nt < 4; nt++)
#pragma unroll
            for (int i = 0; i < 4; i++) acc[mt][nt][i] = 0.f;

    const int crow = tid >> 1;
    const int cseg0 = (tid & 1) * 4;
    const int rot = (crow & 3) * 2;

    auto issue_copy = [&](int c, int s) {
        const int k0 = c * BK;
        const uint32_t base = smem_b + (uint32_t)(s * STG_F) * 4u;
        const float* Asrc = A + (size_t)(bm + crow) * 1024 + k0;
        const float* Bsrc = Bm + (size_t)(bn + crow) * 1024 + k0;
#pragma unroll
        for (int u = 0; u < 4; u++) {
            int seg = cseg0 + u;
            int segp = (seg + rot) & 7;
            cp16(base + (uint32_t)(crow * 128 + segp * 16), Asrc + seg * 4);
            cp16(base + (uint32_t)(A_STG_F * 4 + crow * 128 + segp * 16), Bsrc + seg * 4);
        }
        CP_COMMIT();
    };

    issue_copy(0, 0);
    issue_copy(1, 1);

    const int lr  = lane >> 2;
    const int lc  = lane & 3;
    const int g_rot = (lr & 3) << 2;

    int arow[4], bcol[4];
#pragma unroll
    for (int mt = 0; mt < 4; mt++) arow[mt] = wm * 64 + mt * 16 + lr;
#pragma unroll
    for (int nt = 0; nt < 4; nt++) bcol[nt] = wn * 32 + nt * 8 + lr;

    int stage = 0;
    for (int c = 0; c < KCHUNKS; c++) {
        if (c + 2 < KCHUNKS) { CP_WAIT(1); } else { CP_WAIT(0); }
        __syncthreads();

        const float* As = smemf + stage * STG_F;
        const float* Bs = As + A_STG_F;

        float2 alo[2][4], ahi[2][4], bb[2][4];
        {
            const int gidx = (lc + g_rot) & 15;
#pragma unroll
            for (int mt = 0; mt < 4; mt++) {
                alo[0][mt] = *reinterpret_cast<const float2*>(As + arow[mt] * 32 + 2 * gidx);
                ahi[0][mt] = *reinterpret_cast<const float2*>(As + (arow[mt] + 8) * 32 + 2 * gidx);
            }
#pragma unroll
            for (int nt = 0; nt < 4; nt++)
                bb[0][nt] = *reinterpret_cast<const float2*>(Bs + bcol[nt] * 32 + 2 * gidx);
        }

#pragma unroll
        for (int ks = 0; ks < 4; ks++) {
            const int cur = ks & 1;
            const int nxt = cur ^ 1;
            if (ks < 3) {
                const int gidx = ((ks + 1) * 4 + lc + g_rot) & 15;
#pragma unroll
                for (int mt = 0; mt < 4; mt++) {
                    alo[nxt][mt] = *reinterpret_cast<const float2*>(As + arow[mt] * 32 + 2 * gidx);
                    ahi[nxt][mt] = *reinterpret_cast<const float2*>(As + (arow[mt] + 8) * 32 + 2 * gidx);
                }
#pragma unroll
                for (int nt = 0; nt < 4; nt++)
                    bb[nxt][nt] = *reinterpret_cast<const float2*>(Bs + bcol[nt] * 32 + 2 * gidx);
            }
#pragma unroll
            for (int mt = 0; mt < 4; mt++)
#pragma unroll
                for (int nt = 0; nt < 4; nt++)
                    mma_tf32(acc[mt][nt][0], acc[mt][nt][1], acc[mt][nt][2], acc[mt][nt][3],
                             alo[cur][mt].x, ahi[cur][mt].x, alo[cur][mt].y, ahi[cur][mt].y,
                             bb[cur][nt].x, bb[cur][nt].y);
        }

        if (c + 2 < KCHUNKS) {
            int ns = stage + 2; if (ns >= STAGES) ns -= STAGES;
            issue_copy(c + 2, ns);
        }
        stage++; if (stage >= STAGES) stage = 0;
    }

    const int N = (mode == 0) ? 3 * C_ : C_;
#pragma unroll
    for (int mt = 0; mt < 4; mt++) {
#pragma unroll
        for (int i2 = 0; i2 < 2; i2++) {
            const int r = bm + wm * 64 + mt * 16 + lr + i2 * 8;
#pragma unroll
            for (int nt = 0; nt < 4; nt++) {
                const int c = bn + wn * 32 + nt * 8 + lc * 2;
                float2 v = make_float2(acc[mt][nt][i2 * 2], acc[mt][nt][i2 * 2 + 1]);
                if (mode == 0) {
                    const int which = c >> 10, cc = c & 1023;
                    const int h = cc >> 6, d0 = cc & 63;
                    const int b = r >> 11, tg = r & 2047, g = tg >> 8, t = tg & 255;
                    float* base = (which == 0) ? g_q : (which == 1) ? g_k : g_v;
                    *reinterpret_cast<float2*>(
                        base + ((((size_t)b * NH + h) * NG + g) * GT + t) * HS + d0) = v;
                } else {
                    *reinterpret_cast<float2*>(Cout + (size_t)r * N + c) = v;
                }
            }
        }
    }
}

// ---------------- HMMA flash attention over 257 tokens ----------------
// smem (floats): Ks[257][68] d-perm'd | Vt[64][264] t-perm'd | strips 8x16x68 | qm[68] | wbuf[264]
#define KS_OFF  0
#define KS_STR  68
#define VT_OFF  17476
#define VT_STR  264
#define STR_OFF 34372
#define QM_OFF  43076
#define WB_OFF  43144
#define ATT_F   43408

__global__ __launch_bounds__(256)
void attn_kernel() {
    extern __shared__ float sm[];
    const int id = blockIdx.x;
    const int g = id & 7, h = (id >> 3) & 15, b = id >> 7;
    const int tid = threadIdx.x;
    const int warp = tid >> 5, lane = tid & 31;
    const int lr = lane >> 2, lc = lane & 3;

    const size_t off = (size_t)id * (GT * HS);

    // phase 0: load K (d-perm'd, tf32) and V transposed (t-perm'd, tf32)
    for (int idx = tid; idx < GT * HS; idx += 256) {
        int t = idx >> 6, d = idx & 63;
        sm[KS_OFF + t * KS_STR + kperm(d)] = tf32r(g_k[off + idx]);
        sm[VT_OFF + d * VT_STR + kperm(t)] = tf32r(g_v[off + idx]);
    }
    __syncthreads();

    // phase 1: means
    {
        int which = tid >> 6;
        int d = tid & 63;
        if (which == 0) {            // q mean from gmem (exact)
            float s = 0.f;
#pragma unroll 8
            for (int t = 0; t < GT; t++) s += g_q[off + t * HS + d];
            float m = s * (1.f / 256.f);
            g_qm[(size_t)id * HS + d] = m;
            sm[QM_OFF + kperm(d)] = tf32r(m);
        } else if (which == 1) {     // k mean from gmem (exact)
            float s = 0.f;
#pragma unroll 8
            for (int t = 0; t < GT; t++) s += g_k[off + t * HS + d];
            float m = s * (1.f / 256.f);
            g_km[(size_t)id * HS + d] = m;
            sm[KS_OFF + 256 * KS_STR + kperm(d)] = tf32r(m);
        } else if (which == 2) {     // v mean from Vt (rounded src ok; only used in PV)
            float s = 0.f;
            const float* vp = sm + VT_OFF + d * VT_STR;
#pragma unroll 16
            for (int t = 0; t < GT; t += 4) {
                float4 v = *reinterpret_cast<const float4*>(vp + t);
                s += v.x + v.y + v.z + v.w;
            }
            float m = s * (1.f / 256.f);
            sm[VT_OFF + d * VT_STR + 256] = tf32r(m);
#pragma unroll
            for (int p = 1; p < 8; p++) sm[VT_OFF + d * VT_STR + 256 + p] = 0.f;
        }
    }
    // no sync needed: phase 2 reads only Ks rows 0..255 / Vt cols 0..255 (written in phase 0)

    float* strip = sm + STR_OFF + warp * 16 * KS_STR;

    // phase 2: two query tiles of 128 rows, warp owns 16 rows
#pragma unroll 1
    for (int qt = 0; qt < 2; qt++) {
        const int qb = qt * 128;
        const int r0 = qb + warp * 16 + lr;   // absolute query rows r0, r0+8
        const int nchunks = qt ? 4 : 2;

        // Q A-fragments (held in regs for the whole tile)
        float qa[8][4];
        const float* qrow0 = g_q + off + (size_t)r0 * HS;
        const float* qrow1 = qrow0 + 8 * HS;
#pragma unroll
        for (int ds = 0; ds < 8; ds++) {
            qa[ds][0] = tf32r(qrow0[ds * 8 + lc]);
            qa[ds][1] = tf32r(qrow1[ds * 8 + lc]);
            qa[ds][2] = tf32r(qrow0[ds * 8 + lc + 4]);
            qa[ds][3] = tf32r(qrow1[ds * 8 + lc + 4]);
        }

        float m0 = -1e30f, m1 = -1e30f, l0 = 0.f, l1 = 0.f;
        float o[8][4];
#pragma unroll
        for (int nt = 0; nt < 8; nt++)
#pragma unroll
            for (int i = 0; i < 4; i++) o[nt][i] = 0.f;

#pragma unroll 1
        for (int kc = 0; kc < nchunks; kc++) {
            const int kbase = kc * 64;

            // ---- QK^T: S chunk 16x64 ----
            float s[8][4];
#pragma unroll
            for (int nt = 0; nt < 8; nt++) { s[nt][0] = s[nt][1] = s[nt][2] = s[nt][3] = 0.f; }
#pragma unroll
            for (int nt = 0; nt < 8; nt++) {
                const float* krow = sm + KS_OFF + (kbase + nt * 8 + lr) * KS_STR;
#pragma unroll
                for (int ds = 0; ds < 8; ds++) {
                    float2 bv = *reinterpret_cast<const float2*>(krow + ds * 8 + 2 * lc);
                    mma_tf32(s[nt][0], s[nt][1], s[nt][2], s[nt][3],
                             qa[ds][0], qa[ds][1], qa[ds][2], qa[ds][3], bv.x, bv.y);
                }
            }

            // ---- mask + scale + online softmax ----
            float mx0 = -1e30f, mx1 = -1e30f;
#pragma unroll
            for (int nt = 0; nt < 8; nt++) {
                const int j0 = kbase + nt * 8 + 2 * lc;
                const int j1 = j0 + 1;
                float v0 = s[nt][0] * 0.125f; if (j0 > r0)     v0 = -1e30f;
                float v1 = s[nt][1] * 0.125f; if (j1 > r0)     v1 = -1e30f;
                float v2 = s[nt][2] * 0.125f; if (j0 > r0 + 8) v2 = -1e30f;
                float v3 = s[nt][3] * 0.125f; if (j1 > r0 + 8) v3 = -1e30f;
                s[nt][0] = v0; s[nt][1] = v1; s[nt][2] = v2; s[nt][3] = v3;
                mx0 = fmaxf(mx0, fmaxf(v0, v1));
                mx1 = fmaxf(mx1, fmaxf(v2, v3));
            }
            mx0 = fmaxf(mx0, __shfl_xor_sync(0xffffffffu, mx0, 1));
            mx0 = fmaxf(mx0, __shfl_xor_sync(0xffffffffu, mx0, 2));
            mx1 = fmaxf(mx1, __shfl_xor_sync(0xffffffffu, mx1, 1));
            mx1 = fmaxf(mx1, __shfl_xor_sync(0xffffffffu, mx1, 2));

            const float nm0 = fmaxf(m0, mx0);
            const float nm1 = fmaxf(m1, mx1);
            const float f0 = __expf(m0 - nm0);
            const float f1 = __expf(m1 - nm1);
            m0 = nm0; m1 = nm1;

            float rs0 = 0.f, rs1 = 0.f;
#pragma unroll
            for (int nt = 0; nt < 8; nt++) {
                float p0 = __expf(s[nt][0] - nm0);
                float p1 = __expf(s[nt][1] - nm0);
                float p2 = __expf(s[nt][2] - nm1);
                float p3 = __expf(s[nt][3] - nm1);
                rs0 += p0 + p1; rs1 += p2 + p3;
                // write P strip in A-frag interleaved layout: col nt*8 + perm8(2lc+e)
                const int c0 = nt * 8 + perm8(2 * lc);
                const int c1 = nt * 8 + perm8(2 * lc + 1);
                strip[lr * KS_STR + c0]       = tf32r(p0);
                strip[lr * KS_STR + c1]       = tf32r(p1);
                strip[(lr + 8) * KS_STR + c0] = tf32r(p2);
                strip[(lr + 8) * KS_STR + c1] = tf32r(p3);
            }
            rs0 += __shfl_xor_sync(0xffffffffu, rs0, 1);
            rs0 += __shfl_xor_sync(0xffffffffu, rs0, 2);
            rs1 += __shfl_xor_sync(0xffffffffu, rs1, 1);
            rs1 += __shfl_xor_sync(0xffffffffu, rs1, 2);
            l0 = l0 * f0 + rs0;
            l1 = l1 * f1 + rs1;
#pragma unroll
            for (int nt = 0; nt < 8; nt++) {
                o[nt][0] *= f0; o[nt][1] *= f0;
                o[nt][2] *= f1; o[nt][3] *= f1;
            }
            __syncwarp();

            // ---- PV: O += P @ V ----
            float pa[8][4];
#pragma unroll
            for (int ks = 0; ks < 8; ks++) {
                float2 lo = *reinterpret_cast<const float2*>(strip + lr * KS_STR + ks * 8 + 2 * lc);
                float2 hi = *reinterpret_cast<const float2*>(strip + (lr + 8) * KS_STR + ks * 8 + 2 * lc);
                pa[ks][0] = lo.x; pa[ks][1] = hi.x; pa[ks][2] = lo.y; pa[ks][3] = hi.y;
            }
#pragma unroll
            for (int nt = 0; nt < 8; nt++) {
                const float* vrow = sm + VT_OFF + (nt * 8 + lr) * VT_STR + kbase;
#pragma unroll
                for (int ks = 0; ks < 8; ks++) {
                    float2 bv = *reinterpret_cast<const float2*>(vrow + ks * 8 + 2 * lc);
                    mma_tf32(o[nt][0], o[nt][1], o[nt][2], o[nt][3],
                             pa[ks][0], pa[ks][1], pa[ks][2], pa[ks][3], bv.x, bv.y);
                }
            }
            __syncwarp();
        }

        // ---- finalize tile: O /= l, write g_xo (rows all < 256) ----
        const float inv0 = 1.f / l0;
        const float inv1 = 1.f / l1;
        float* x0 = g_xo + ((size_t)b * T_ + g * GT + r0) * C_ + h * HS;
        float* x1 = x0 + (size_t)8 * C_;
#pragma unroll
        for (int nt = 0; nt < 8; nt++) {
            const int c0 = nt * 8 + perm8(2 * lc);
            const int c1 = nt * 8 + perm8(2 * lc + 1);
            x0[c0] = tf32r(o[nt][0] * inv0);
            x0[c1] = tf32r(o[nt][1] * inv0);
            x1[c0] = tf32r(o[nt][2] * inv1);
            x1[c1] = tf32r(o[nt][3] * inv1);
        }
    }

    __syncthreads();

    // phase 3: mean-query (row 256) scalar path, warp 0
    if (warp == 0) {
        float* wbuf = sm + WB_OFF;
        if (lane < 7) wbuf[257 + lane] = 0.f;
        const float* qm = sm + QM_OFF;
        float mx = -1e30f;
        float sc[9];
        for (int j = lane, u = 0; j < LQ; j += 32, u++) {
            const float4* kp = reinterpret_cast<const float4*>(sm + KS_OFF + j * KS_STR);
            const float4* qp = reinterpret_cast<const float4*>(qm);
            float s = 0.f;
#pragma unroll
            for (int dd = 0; dd < 16; dd++) {
                float4 kv = kp[dd], qv = qp[dd];
                s += qv.x * kv.x + qv.y * kv.y + qv.z * kv.z + qv.w * kv.w;
            }
            s *= 0.125f;
            sc[u] = s;
            mx = fmaxf(mx, s);
        }
#pragma unroll
        for (int o2 = 16; o2; o2 >>= 1) mx = fmaxf(mx, __shfl_xor_sync(0xffffffffu, mx, o2));
        float sum = 0.f;
        for (int j = lane, u = 0; j < LQ; j += 32, u++) {
            float e = __expf(sc[u] - mx);
            wbuf[kperm(j)] = e;            // scatter in Vt-permuted order
            sum += e;
        }
#pragma unroll
        for (int o2 = 16; o2; o2 >>= 1) sum += __shfl_xor_sync(0xffffffffu, sum, o2);
        const float inv = 1.f / sum;
        __syncwarp();
#pragma unroll
        for (int dh = 0; dh < 2; dh++) {
            const int d = lane + dh * 32;
            const float* vp = sm + VT_OFF + d * VT_STR;
            float acc = 0.f;
#pragma unroll 8
            for (int j = 0; j < 264; j += 4) {
                float4 w = *reinterpret_cast<const float4*>(wbuf + j);
                float4 v = *reinterpret_cast<const float4*>(vp + j);
                acc += w.x * v.x + w.y * v.y + w.z * v.z + w.w * v.w;
            }
            g_attm[(size_t)id * HS + d] = acc * inv;
        }
    }
}

// ---------------- level-2 tiny 7x7 causal attention + y outputs ----------------
__global__ void second_kernel(float* __restrict__ out) {
    __shared__ float q7[7][64], k7[7][64], a7[7][64];
    __shared__ float S[7][8], W[7][8];
    const int id = blockIdx.x;
    const int tid = threadIdx.x;

    for (int idx = tid; idx < 7 * 64; idx += 64) {
        int j = idx >> 6, d = idx & 63;
        q7[j][d] = g_qm[((size_t)id * NG + j) * HS + d];
        k7[j][d] = g_km[((size_t)id * NG + j) * HS + d];
        a7[j][d] = g_attm[((size_t)id * NG + j) * HS + d];
    }
    __syncthreads();

    if (tid < 28) {
        int p = tid, j = 0;
        while ((j + 1) * (j + 2) / 2 <= p) j++;
        int jp = p - j * (j + 1) / 2;
        float s = 0.f;
#pragma unroll
        for (int dd = 0; dd < 64; dd++) s += q7[j][dd] * k7[jp][dd];
        S[j][jp] = s * 0.125f;
    }
    __syncthreads();

    if (tid < 7) {
        int j = tid;
        float mx = -1e30f;
        for (int jp = 0; jp <= j; jp++) mx = fmaxf(mx, S[j][jp]);
        float sum = 0.f;
        for (int jp = 0; jp <= j; jp++) { float e = __expf(S[j][jp] - mx); W[j][jp] = e; sum += e; }
        float inv = 1.f / sum;
        for (int jp = 0; jp <= j; jp++) W[j][jp] *= inv;
    }
    __syncthreads();

    const size_t yq_off = (size_t)B_ * T_ * C_;
    const size_t ylen   = (size_t)B_ * NH * 7 * HS;
    int d = tid;
    for (int j = 0; j < 7; j++) {
        float acc = 0.f;
        for (int jp = 0; jp <= j; jp++) acc += W[j][jp] * a7[jp][d];
        size_t o = ((size_t)id * 7 + j) * HS + d;
        out[yq_off            + o] = q7[j][d];
        out[yq_off +     ylen + o] = k7[j][d];
        out[yq_off + 2 * ylen + o] = acc;
    }
}

// ---------------- launch ----------------
extern "C" void kernel_launch(void* const* d_in, const int* in_sizes, int n_in,
                              void* d_out, int out_size) {
    (void)in_sizes; (void)n_in; (void)out_size;
    const float* x      = (const float*)d_in[0];
    const float* W_attn = (const float*)d_in[1];
    const float* W_proj = (const float*)d_in[2];
    float* out = (float*)d_out;

    round_ilv_kernel<<<B_*T_*C_/2048, 256>>>(x, 0);
    roundT_kernel<<<dim3(96, 32), 256>>>(W_attn, 3 * C_, 1);
    roundT_kernel<<<dim3(32, 32), 256>>>(W_proj, C_, 2);

    const int gemm_smem = STAGES * STG_F * (int)sizeof(float);
    cudaFuncSetAttribute(gemm_tf32_kernel, cudaFuncAttributeMaxDynamicSharedMemorySize, gemm_smem);

    gemm_tf32_kernel<<<dim3(128, 24), 256, gemm_smem>>>(nullptr, 0);

    const int att_smem = ATT_F * (int)sizeof(float);   // 173632
    cudaFuncSetAttribute(attn_kernel, cudaFuncAttributeMaxDynamicSharedMemorySize, att_smem);
    attn_kernel<<<B_ * NH * NG, 256, att_smem>>>();

    second_kernel<<<B_ * NH, 64>>>(out);

    gemm_tf32_kernel<<<dim3(128, 8), 256, gemm_smem>>>(out, 1);
}

// round 11
// speedup vs baseline: 2.6935x; 1.4885x over previous
#include <cuda_runtime.h>
#include <cuda_fp16.h>
#include <cstdint>

#define B_  8
#define T_  2048
#define C_  1024
#define NH  16
#define HS  64
#define NG  8
#define GT  256
#define LQ  257

// ---------------- device scratch ----------------
__device__ float g_q[B_*NH*NG*GT*HS];
__device__ float g_k[B_*NH*NG*GT*HS];
__device__ float g_v[B_*NH*NG*GT*HS];
__device__ float g_qm[B_*NH*NG*HS];
__device__ float g_km[B_*NH*NG*HS];
__device__ float g_vm[B_*NH*NG*HS];
__device__ float g_attm[B_*NH*NG*HS];
__device__ __half h_xr[B_*T_*C_];         // x, fp16 + k16-interleaved
__device__ __half h_xo[B_*T_*C_];         // attn out, fp16 + k16-interleaved
__device__ __half h_War[3*C_*C_];         // W_attn^T [3072][1024] fp16 interleaved
__device__ __half h_WpR[C_*C_];           // W_proj^T [1024][1024] fp16 interleaved

// ---- permutation helpers ----
// attention-internal (tf32 pairs): pairs (k, k+4) adjacent within 8
__device__ __forceinline__ int perm8(int k)  { return ((k & 3) << 1) | ((k >> 2) & 1); }
__device__ __forceinline__ int kperm(int k)  { return (k & ~7) | perm8(k & 7); }
// fp16 m16n8k16 fragment interleave within groups of 16:
// k -> 4*((k>>1)&3) + 2*((k>>3)&1) + (k&1)
__device__ __forceinline__ int idx16(int k)  { return (((k >> 1) & 3) << 2) | (((k >> 3) & 1) << 1) | (k & 1); }
__device__ __forceinline__ int pos16(int k)  { return (k & ~15) | idx16(k & 15); }

__device__ __forceinline__ float tf32r(float x) {
    unsigned r;
    asm("cvt.rna.tf32.f32 %0, %1;" : "=r"(r) : "f"(x));
    return __uint_as_float(r);
}

__device__ __forceinline__ uint32_t smem_u32(const void* p) {
    uint32_t a;
    asm("{ .reg .u64 t; cvta.to.shared.u64 t, %1; cvt.u32.u64 %0, t; }" : "=r"(a) : "l"(p));
    return a;
}

__device__ __forceinline__ void cp16(uint32_t dst, const void* src) {
    asm volatile("cp.async.cg.shared.global [%0], [%1], 16;\n" :: "r"(dst), "l"(src));
}
#define CP_COMMIT() asm volatile("cp.async.commit_group;\n" ::: "memory")
#define CP_WAIT(n)  asm volatile("cp.async.wait_group %0;\n" :: "n"(n) : "memory")

// fp16 tensor-core MMA, fp32 accumulate
__device__ __forceinline__ void mma_f16(float& c0, float& c1, float& c2, float& c3,
                                        uint32_t a0, uint32_t a1, uint32_t a2, uint32_t a3,
                                        uint32_t b0, uint32_t b1) {
    asm volatile(
        "mma.sync.aligned.m16n8k16.row.col.f32.f16.f16.f32 "
        "{%0,%1,%2,%3}, {%4,%5,%6,%7}, {%8,%9}, {%0,%1,%2,%3};\n"
        : "+f"(c0), "+f"(c1), "+f"(c2), "+f"(c3)
        : "r"(a0), "r"(a1), "r"(a2), "r"(a3), "r"(b0), "r"(b1));
}

// tf32 MMA (attention)
__device__ __forceinline__ void mma_tf32(float& c0, float& c1, float& c2, float& c3,
                                         float a0, float a1, float a2, float a3,
                                         float b0, float b1) {
    asm volatile(
        "mma.sync.aligned.m16n8k8.row.col.f32.tf32.tf32.f32 "
        "{%0,%1,%2,%3}, {%4,%5,%6,%7}, {%8,%9}, {%0,%1,%2,%3};\n"
        : "+f"(c0), "+f"(c1), "+f"(c2), "+f"(c3)
        : "r"(__float_as_uint(a0)), "r"(__float_as_uint(a1)),
          "r"(__float_as_uint(a2)), "r"(__float_as_uint(a3)),
          "r"(__float_as_uint(b0)), "r"(__float_as_uint(b1)));
}

// ---------------- conversion kernels ----------------
// x -> h_xr: fp16, k16-interleaved. 16 elems per thread.
__global__ void cvt_x_kernel(const float* __restrict__ src) {
    size_t base = ((size_t)blockIdx.x * 256 + threadIdx.x) * 16;
    float s[16];
#pragma unroll
    for (int u = 0; u < 4; u++)
        *reinterpret_cast<float4*>(s + u * 4) = *reinterpret_cast<const float4*>(src + base + u * 4);
    __half2 h[8];
#pragma unroll
    for (int i = 0; i < 8; i++) {
        int k0 = ((i >> 1) << 1) + ((i & 1) << 3);   // dst h2[i] = (s[k0], s[k0+1])
        h[i] = __floats2half2_rn(s[k0], s[k0 + 1]);
    }
    *reinterpret_cast<uint4*>(h_xr + base)     = *reinterpret_cast<uint4*>(h);
    *reinterpret_cast<uint4*>(h_xr + base + 8) = *reinterpret_cast<uint4*>(h + 4);
}

// W[K=1024][N] -> Wt[N][1024] fp16 transposed + interleaved
__global__ void cvt_W_kernel(const float* __restrict__ W, int N, int which) {
    __half* Wt = (which == 1) ? h_War : h_WpR;
    __shared__ float tile[32][33];
    int bx = blockIdx.x * 32;   // n
    int by = blockIdx.y * 32;   // k
    int tx = threadIdx.x & 31, ty = threadIdx.x >> 5;
#pragma unroll
    for (int yy = ty; yy < 32; yy += 8)
        tile[yy][tx] = W[(size_t)(by + yy) * N + bx + tx];
    __syncthreads();
#pragma unroll
    for (int yy = ty; yy < 32; yy += 8) {
        int n = bx + yy, k = by + tx;
        Wt[(size_t)n * 1024 + pos16(k)] = __float2half_rn(tile[tx][yy]);
    }
}

// ---------------- fp16 pipelined GEMM: C[M,N] = A[M,1024] @ Wt[N,1024]^T ----------------
#define BK 32
#define KCHUNKS 32
#define STAGES 4
#define STG_BYTES 16384            // A 8KB + B 8KB per stage

__global__ __launch_bounds__(256, 2)
void gemm_f16_kernel(float* __restrict__ Cout, int mode) {
    extern __shared__ __align__(16) char smc[];
    const uint32_t stg_b = smem_u32(smc);

    const __half* __restrict__ Ah = (mode == 0) ? h_xr  : h_xo;
    const __half* __restrict__ Bh = (mode == 0) ? h_War : h_WpR;

    const int tid  = threadIdx.x;
    const int warp = tid >> 5;
    const int lane = tid & 31;
    const int wm   = warp & 1;
    const int wn   = warp >> 1;
    const int bm   = blockIdx.x * 128;
    const int bn   = blockIdx.y * 128;

    float acc[4][4][4];
#pragma unroll
    for (int mt = 0; mt < 4; mt++)
#pragma unroll
        for (int nt = 0; nt < 4; nt++)
#pragma unroll
            for (int i = 0; i < 4; i++) acc[mt][nt][i] = 0.f;

    // copy coords: thread handles row tid>>1, chunks {0,1} or {2,3}
    const int crow = tid >> 1;
    const int cc0  = (tid & 1) * 2;

    auto issue_copy = [&](int c, int s) {
        const int k0 = c * BK;
        const uint32_t sa = stg_b + (uint32_t)(s * STG_BYTES);
        const uint32_t sb = sa + 8192u;
        const __half* Asrc = Ah + (size_t)(bm + crow) * 1024 + k0;
        const __half* Bsrc = Bh + (size_t)(bn + crow) * 1024 + k0;
#pragma unroll
        for (int u = 0; u < 2; u++) {
            int cidx = cc0 + u;
            uint32_t d = (uint32_t)(crow * 64 + 16 * ((cidx + crow) & 3));
            cp16(sa + d, Asrc + cidx * 8);
            cp16(sb + d, Bsrc + cidx * 8);
        }
        CP_COMMIT();
    };

    issue_copy(0, 0);
    issue_copy(1, 1);
    issue_copy(2, 2);

    const int lr = lane >> 2;
    const int lc = lane & 3;

    int arow[4], bcol[4];
#pragma unroll
    for (int mt = 0; mt < 4; mt++) arow[mt] = wm * 64 + mt * 16 + lr;
#pragma unroll
    for (int nt = 0; nt < 4; nt++) bcol[nt] = wn * 32 + nt * 8 + lr;

    int stage = 0;
    for (int c = 0; c < KCHUNKS; c++) {
        if (c + 2 < KCHUNKS)      { CP_WAIT(2); }
        else if (c + 1 < KCHUNKS) { CP_WAIT(1); }
        else                      { CP_WAIT(0); }
        __syncthreads();

        if (c + 3 < KCHUNKS) {
            int ns = stage + 3; if (ns >= STAGES) ns -= STAGES;
            issue_copy(c + 3, ns);
        }

        const char* As = smc + stage * STG_BYTES;
        const char* Bs = As + 8192;

#pragma unroll
        for (int g16 = 0; g16 < 2; g16++) {
            // fragment byte offset (same for every fragment row: row&3 == lr&3)
            const int gr = (2 * g16 + (lc >> 1) + lr) & 3;
            const int fo = 16 * gr + 8 * (lc & 1);

            uint2 alo[4], ahi[4], bb[4];
#pragma unroll
            for (int mt = 0; mt < 4; mt++) {
                alo[mt] = *reinterpret_cast<const uint2*>(As + arow[mt] * 64 + fo);
                ahi[mt] = *reinterpret_cast<const uint2*>(As + (arow[mt] + 8) * 64 + fo);
            }
#pragma unroll
            for (int nt = 0; nt < 4; nt++)
                bb[nt] = *reinterpret_cast<const uint2*>(Bs + bcol[nt] * 64 + fo);

#pragma unroll
            for (int mt = 0; mt < 4; mt++)
#pragma unroll
                for (int nt = 0; nt < 4; nt++)
                    mma_f16(acc[mt][nt][0], acc[mt][nt][1], acc[mt][nt][2], acc[mt][nt][3],
                            alo[mt].x, ahi[mt].x, alo[mt].y, ahi[mt].y,
                            bb[nt].x, bb[nt].y);
        }
        stage++; if (stage >= STAGES) stage = 0;
    }

    const int N = (mode == 0) ? 3 * C_ : C_;
#pragma unroll
    for (int mt = 0; mt < 4; mt++) {
#pragma unroll
        for (int i2 = 0; i2 < 2; i2++) {
            const int r = bm + wm * 64 + mt * 16 + lr + i2 * 8;
#pragma unroll
            for (int nt = 0; nt < 4; nt++) {
                const int c = bn + wn * 32 + nt * 8 + lc * 2;
                float2 v = make_float2(acc[mt][nt][i2 * 2], acc[mt][nt][i2 * 2 + 1]);
                if (mode == 0) {
                    const int which = c >> 10, cc = c & 1023;
                    const int h = cc >> 6, d0 = cc & 63;
                    const int b = r >> 11, tg = r & 2047, g = tg >> 8, t = tg & 255;
                    float* base = (which == 0) ? g_q : (which == 1) ? g_k : g_v;
                    *reinterpret_cast<float2*>(
                        base + ((((size_t)b * NH + h) * NG + g) * GT + t) * HS + d0) = v;
                } else {
                    *reinterpret_cast<float2*>(Cout + (size_t)r * N + c) = v;
                }
            }
        }
    }
}

// ---------------- HMMA flash attention over 257 tokens ----------------
#define KS_OFF  0
#define KS_STR  68
#define VT_OFF  17476
#define VT_STR  264
#define STR_OFF 34372
#define QM_OFF  43076
#define WB_OFF  43144
#define ATT_F   43408

__global__ __launch_bounds__(256)
void attn_kernel() {
    extern __shared__ float sm[];
    const int id = blockIdx.x;
    const int g = id & 7, h = (id >> 3) & 15, b = id >> 7;
    const int tid = threadIdx.x;
    const int warp = tid >> 5, lane = tid & 31;
    const int lr = lane >> 2, lc = lane & 3;

    const size_t off = (size_t)id * (GT * HS);

    for (int idx = tid; idx < GT * HS; idx += 256) {
        int t = idx >> 6, d = idx & 63;
        sm[KS_OFF + t * KS_STR + kperm(d)] = tf32r(g_k[off + idx]);
        sm[VT_OFF + d * VT_STR + kperm(t)] = tf32r(g_v[off + idx]);
    }
    __syncthreads();

    {
        int which = tid >> 6;
        int d = tid & 63;
        if (which == 0) {
            float s = 0.f;
#pragma unroll 8
            for (int t = 0; t < GT; t++) s += g_q[off + t * HS + d];
            float m = s * (1.f / 256.f);
            g_qm[(size_t)id * HS + d] = m;
            sm[QM_OFF + kperm(d)] = tf32r(m);
        } else if (which == 1) {
            float s = 0.f;
#pragma unroll 8
            for (int t = 0; t < GT; t++) s += g_k[off + t * HS + d];
            float m = s * (1.f / 256.f);
            g_km[(size_t)id * HS + d] = m;
            sm[KS_OFF + 256 * KS_STR + kperm(d)] = tf32r(m);
        } else if (which == 2) {
            float s = 0.f;
            const float* vp = sm + VT_OFF + d * VT_STR;
#pragma unroll 16
            for (int t = 0; t < GT; t += 4) {
                float4 v = *reinterpret_cast<const float4*>(vp + t);
                s += v.x + v.y + v.z + v.w;
            }
            float m = s * (1.f / 256.f);
            sm[VT_OFF + d * VT_STR + 256] = tf32r(m);
#pragma unroll
            for (int p = 1; p < 8; p++) sm[VT_OFF + d * VT_STR + 256 + p] = 0.f;
        }
    }

    float* strip = sm + STR_OFF + warp * 16 * KS_STR;

#pragma unroll 1
    for (int qt = 0; qt < 2; qt++) {
        const int qb = qt * 128;
        const int r0 = qb + warp * 16 + lr;
        const int nchunks = qt ? 4 : 2;

        float qa[8][4];
        const float* qrow0 = g_q + off + (size_t)r0 * HS;
        const float* qrow1 = qrow0 + 8 * HS;
#pragma unroll
        for (int ds = 0; ds < 8; ds++) {
            qa[ds][0] = tf32r(qrow0[ds * 8 + lc]);
            qa[ds][1] = tf32r(qrow1[ds * 8 + lc]);
            qa[ds][2] = tf32r(qrow0[ds * 8 + lc + 4]);
            qa[ds][3] = tf32r(qrow1[ds * 8 + lc + 4]);
        }

        float m0 = -1e30f, m1 = -1e30f, l0 = 0.f, l1 = 0.f;
        float o[8][4];
#pragma unroll
        for (int nt = 0; nt < 8; nt++)
#pragma unroll
            for (int i = 0; i < 4; i++) o[nt][i] = 0.f;

#pragma unroll 1
        for (int kc = 0; kc < nchunks; kc++) {
            const int kbase = kc * 64;

            float s[8][4];
#pragma unroll
            for (int nt = 0; nt < 8; nt++) { s[nt][0] = s[nt][1] = s[nt][2] = s[nt][3] = 0.f; }
#pragma unroll
            for (int nt = 0; nt < 8; nt++) {
                const float* krow = sm + KS_OFF + (kbase + nt * 8 + lr) * KS_STR;
#pragma unroll
                for (int ds = 0; ds < 8; ds++) {
                    float2 bv = *reinterpret_cast<const float2*>(krow + ds * 8 + 2 * lc);
                    mma_tf32(s[nt][0], s[nt][1], s[nt][2], s[nt][3],
                             qa[ds][0], qa[ds][1], qa[ds][2], qa[ds][3], bv.x, bv.y);
                }
            }

            float mx0 = -1e30f, mx1 = -1e30f;
#pragma unroll
            for (int nt = 0; nt < 8; nt++) {
                const int j0 = kbase + nt * 8 + 2 * lc;
                const int j1 = j0 + 1;
                float v0 = s[nt][0] * 0.125f; if (j0 > r0)     v0 = -1e30f;
                float v1 = s[nt][1] * 0.125f; if (j1 > r0)     v1 = -1e30f;
                float v2 = s[nt][2] * 0.125f; if (j0 > r0 + 8) v2 = -1e30f;
                float v3 = s[nt][3] * 0.125f; if (j1 > r0 + 8) v3 = -1e30f;
                s[nt][0] = v0; s[nt][1] = v1; s[nt][2] = v2; s[nt][3] = v3;
                mx0 = fmaxf(mx0, fmaxf(v0, v1));
                mx1 = fmaxf(mx1, fmaxf(v2, v3));
            }
            mx0 = fmaxf(mx0, __shfl_xor_sync(0xffffffffu, mx0, 1));
            mx0 = fmaxf(mx0, __shfl_xor_sync(0xffffffffu, mx0, 2));
            mx1 = fmaxf(mx1, __shfl_xor_sync(0xffffffffu, mx1, 1));
            mx1 = fmaxf(mx1, __shfl_xor_sync(0xffffffffu, mx1, 2));

            const float nm0 = fmaxf(m0, mx0);
            const float nm1 = fmaxf(m1, mx1);
            const float f0 = __expf(m0 - nm0);
            const float f1 = __expf(m1 - nm1);
            m0 = nm0; m1 = nm1;

            float rs0 = 0.f, rs1 = 0.f;
#pragma unroll
            for (int nt = 0; nt < 8; nt++) {
                float p0 = __expf(s[nt][0] - nm0);
                float p1 = __expf(s[nt][1] - nm0);
                float p2 = __expf(s[nt][2] - nm1);
                float p3 = __expf(s[nt][3] - nm1);
                rs0 += p0 + p1; rs1 += p2 + p3;
                const int c0 = nt * 8 + perm8(2 * lc);
                const int c1 = nt * 8 + perm8(2 * lc + 1);
                strip[lr * KS_STR + c0]       = tf32r(p0);
                strip[lr * KS_STR + c1]       = tf32r(p1);
                strip[(lr + 8) * KS_STR + c0] = tf32r(p2);
                strip[(lr + 8) * KS_STR + c1] = tf32r(p3);
            }
            rs0 += __shfl_xor_sync(0xffffffffu, rs0, 1);
            rs0 += __shfl_xor_sync(0xffffffffu, rs0, 2);
            rs1 += __shfl_xor_sync(0xffffffffu, rs1, 1);
            rs1 += __shfl_xor_sync(0xffffffffu, rs1, 2);
            l0 = l0 * f0 + rs0;
            l1 = l1 * f1 + rs1;
#pragma unroll
            for (int nt = 0; nt < 8; nt++) {
                o[nt][0] *= f0; o[nt][1] *= f0;
                o[nt][2] *= f1; o[nt][3] *= f1;
            }
            __syncwarp();

            float pa[8][4];
#pragma unroll
            for (int ks = 0; ks < 8; ks++) {
                float2 lo = *reinterpret_cast<const float2*>(strip + lr * KS_STR + ks * 8 + 2 * lc);
                float2 hi = *reinterpret_cast<const float2*>(strip + (lr + 8) * KS_STR + ks * 8 + 2 * lc);
                pa[ks][0] = lo.x; pa[ks][1] = hi.x; pa[ks][2] = lo.y; pa[ks][3] = hi.y;
            }
#pragma unroll
            for (int nt = 0; nt < 8; nt++) {
                const float* vrow = sm + VT_OFF + (nt * 8 + lr) * VT_STR + kbase;
#pragma unroll
                for (int ks = 0; ks < 8; ks++) {
                    float2 bv = *reinterpret_cast<const float2*>(vrow + ks * 8 + 2 * lc);
                    mma_tf32(o[nt][0], o[nt][1], o[nt][2], o[nt][3],
                             pa[ks][0], pa[ks][1], pa[ks][2], pa[ks][3], bv.x, bv.y);
                }
            }
            __syncwarp();
        }

        // finalize: write fp16 k16-interleaved h_xo (proj GEMM's A operand)
        const float inv0 = 1.f / l0;
        const float inv1 = 1.f / l1;
        __half* x0 = h_xo + ((size_t)b * T_ + g * GT + r0) * C_ + h * HS;
        __half* x1 = x0 + (size_t)8 * C_;
#pragma unroll
        for (int nt = 0; nt < 8; nt++) {
            const int p = 16 * (nt >> 1) + 4 * lc + 2 * (nt & 1);
            *reinterpret_cast<__half2*>(x0 + p) = __floats2half2_rn(o[nt][0] * inv0, o[nt][1] * inv0);
            *reinterpret_cast<__half2*>(x1 + p) = __floats2half2_rn(o[nt][2] * inv1, o[nt][3] * inv1);
        }
    }

    __syncthreads();

    if (warp == 0) {
        float* wbuf = sm + WB_OFF;
        if (lane < 7) wbuf[257 + lane] = 0.f;
        const float* qm = sm + QM_OFF;
        float mx = -1e30f;
        float sc[9];
        for (int j = lane, u = 0; j < LQ; j += 32, u++) {
            const float4* kp = reinterpret_cast<const float4*>(sm + KS_OFF + j * KS_STR);
            const float4* qp = reinterpret_cast<const float4*>(qm);
            float s = 0.f;
#pragma unroll
            for (int dd = 0; dd < 16; dd++) {
                float4 kv = kp[dd], qv = qp[dd];
                s += qv.x * kv.x + qv.y * kv.y + qv.z * kv.z + qv.w * kv.w;
            }
            s *= 0.125f;
            sc[u] = s;
            mx = fmaxf(mx, s);
        }
#pragma unroll
        for (int o2 = 16; o2; o2 >>= 1) mx = fmaxf(mx, __shfl_xor_sync(0xffffffffu, mx, o2));
        float sum = 0.f;
        for (int j = lane, u = 0; j < LQ; j += 32, u++) {
            float e = __expf(sc[u] - mx);
            wbuf[kperm(j)] = e;
            sum += e;
        }
#pragma unroll
        for (int o2 = 16; o2; o2 >>= 1) sum += __shfl_xor_sync(0xffffffffu, sum, o2);
        const float inv = 1.f / sum;
        __syncwarp();
#pragma unroll
        for (int dh = 0; dh < 2; dh++) {
            const int d = lane + dh * 32;
            const float* vp = sm + VT_OFF + d * VT_STR;
            float acc = 0.f;
#pragma unroll 8
            for (int j = 0; j < 264; j += 4) {
                float4 w = *reinterpret_cast<const float4*>(wbuf + j);
                float4 v = *reinterpret_cast<const float4*>(vp + j);
                acc += w.x * v.x + w.y * v.y + w.z * v.z + w.w * v.w;
            }
            g_attm[(size_t)id * HS + d] = acc * inv;
        }
    }
}

// ---------------- level-2 tiny 7x7 causal attention + y outputs ----------------
__global__ void second_kernel(float* __restrict__ out) {
    __shared__ float q7[7][64], k7[7][64], a7[7][64];
    __shared__ float S[7][8], W[7][8];
    const int id = blockIdx.x;
    const int tid = threadIdx.x;

    for (int idx = tid; idx < 7 * 64; idx += 64) {
        int j = idx >> 6, d = idx & 63;
        q7[j][d] = g_qm[((size_t)id * NG + j) * HS + d];
        k7[j][d] = g_km[((size_t)id * NG + j) * HS + d];
        a7[j][d] = g_attm[((size_t)id * NG + j) * HS + d];
    }
    __syncthreads();

    if (tid < 28) {
        int p = tid, j = 0;
        while ((j + 1) * (j + 2) / 2 <= p) j++;
        int jp = p - j * (j + 1) / 2;
        float s = 0.f;
#pragma unroll
        for (int dd = 0; dd < 64; dd++) s += q7[j][dd] * k7[jp][dd];
        S[j][jp] = s * 0.125f;
    }
    __syncthreads();

    if (tid < 7) {
        int j = tid;
        float mx = -1e30f;
        for (int jp = 0; jp <= j; jp++) mx = fmaxf(mx, S[j][jp]);
        float sum = 0.f;
        for (int jp = 0; jp <= j; jp++) { float e = __expf(S[j][jp] - mx); W[j][jp] = e; sum += e; }
        float inv = 1.f / sum;
        for (int jp = 0; jp <= j; jp++) W[j][jp] *= inv;
    }
    __syncthreads();

    const size_t yq_off = (size_t)B_ * T_ * C_;
    const size_t ylen   = (size_t)B_ * NH * 7 * HS;
    int d = tid;
    for (int j = 0; j < 7; j++) {
        float acc = 0.f;
        for (int jp = 0; jp <= j; jp++) acc += W[j][jp] * a7[jp][d];
        size_t o = ((size_t)id * 7 + j) * HS + d;
        out[yq_off            + o] = q7[j][d];
        out[yq_off +     ylen + o] = k7[j][d];
        out[yq_off + 2 * ylen + o] = acc;
    }
}

// ---------------- launch ----------------
extern "C" void kernel_launch(void* const* d_in, const int* in_sizes, int n_in,
                              void* d_out, int out_size) {
    (void)in_sizes; (void)n_in; (void)out_size;
    const float* x      = (const float*)d_in[0];
    const float* W_attn = (const float*)d_in[1];
    const float* W_proj = (const float*)d_in[2];
    float* out = (float*)d_out;

    cvt_x_kernel<<<B_*T_*C_/4096, 256>>>(x);
    cvt_W_kernel<<<dim3(96, 32), 256>>>(W_attn, 3 * C_, 1);
    cvt_W_kernel<<<dim3(32, 32), 256>>>(W_proj, C_, 2);

    const int gemm_smem = STAGES * STG_BYTES;   // 65536
    cudaFuncSetAttribute(gemm_f16_kernel, cudaFuncAttributeMaxDynamicSharedMemorySize, gemm_smem);

    // qkv = x @ W_attn  (M=16384, N=3072)
    gemm_f16_kernel<<<dim3(128, 24), 256, gemm_smem>>>(nullptr, 0);

    const int att_smem = ATT_F * (int)sizeof(float);
    cudaFuncSetAttribute(attn_kernel, cudaFuncAttributeMaxDynamicSharedMemorySize, att_smem);
    attn_kernel<<<B_ * NH * NG, 256, att_smem>>>();

    second_kernel<<<B_ * NH, 64>>>(out);

    // out = xo @ W_proj  (M=16384, N=1024)
    gemm_f16_kernel<<<dim3(128, 8), 256, gemm_smem>>>(out, 1);
}